// round 8
// baseline (speedup 1.0000x reference)
#include <cuda_runtime.h>
#include <cuda_bf16.h>
#include <math.h>
#include <stdint.h>

// ---------------------------------------------------------------------------
// Problem constants
// ---------------------------------------------------------------------------
#define BSZ     2
#define LSEQ    1024
#define DMODEL  1024
#define DINNER  2048
#define DSTATE  16
#define DTRANK  64
#define MROWS   (BSZ * LSEQ)        // 2048
#define NXZ     (2 * DINNER)        // 4096
#define NDBC    (DTRANK + 2*DSTATE) // 96
#define SPLITK_XPROJ 8

// Dynamic smem for the tensor GEMM: 2 stages x (16KB A + 16KB B) + align slack
#define TG_STAGE_BYTES 32768
#define TG_SMEM_BYTES  (2 * TG_STAGE_BYTES + 1024)

// tcgen05 is only legal on arch-specific ("a") targets. The harness also
// compiles a plain compute_103/sm_103 pass; give that pass an mma.sync path.
#if defined(__CUDA_ARCH_FEAT_SM103_ALL) || defined(__CUDA_ARCH_FEAT_SM100_ALL) || defined(__CUDA_ARCH_FEAT_SM101_ALL)
#define HAS_TCGEN05 1
#else
#define HAS_TCGEN05 0
#endif

// ---------------------------------------------------------------------------
// Scratch (static device memory; no allocations allowed)
// ---------------------------------------------------------------------------
__device__ float g_xz[MROWS * NXZ];                       // (xs | z)
__device__ float g_xsc[MROWS * DINNER];                   // conv+silu output
__device__ float g_dbc_part[SPLITK_XPROJ * MROWS * NDBC];
__device__ float g_dbc[MROWS * NDBC];
__device__ float g_delta[MROWS * DINNER];
__device__ float g_y[MROWS * DINNER];                     // gated scan output

// ---------------------------------------------------------------------------
// Small PTX helpers
// ---------------------------------------------------------------------------
__device__ __forceinline__ unsigned f2tf32(float x) {
    unsigned r;
    asm("cvt.rna.tf32.f32 %0, %1;" : "=r"(r) : "f"(x));
    return r;
}

__device__ __forceinline__ uint32_t smem_u32(const void* p) {
    uint32_t a;
    asm("{ .reg .u64 t; cvta.to.shared.u64 t, %1; cvt.u32.u64 %0, t; }"
        : "=r"(a) : "l"(p));
    return a;
}

#if HAS_TCGEN05
__device__ __forceinline__ uint32_t elect_one() {
    uint32_t pred;
    asm volatile("{\n .reg .pred p;\n elect.sync _|p, 0xFFFFFFFF;\n"
                 " selp.b32 %0, 1, 0, p;\n}" : "=r"(pred));
    return pred;
}

__device__ __forceinline__ void mbar_init(uint32_t addr, uint32_t cnt) {
    asm volatile("mbarrier.init.shared.b64 [%0], %1;" :: "r"(addr), "r"(cnt) : "memory");
}
__device__ __forceinline__ void mbar_inval(uint32_t addr) {
    asm volatile("mbarrier.inval.shared.b64 [%0];" :: "r"(addr) : "memory");
}
__device__ __forceinline__ void mbar_wait_parity(uint32_t addr, uint32_t parity) {
    asm volatile(
        "{\n .reg .pred P;\n"
        "WAIT_%=:\n"
        " mbarrier.try_wait.parity.acquire.cta.shared::cta.b64 P, [%0], %1, 0x989680;\n"
        " @P bra.uni DONE_%=;\n"
        " bra.uni WAIT_%=;\n"
        "DONE_%=:\n}"
        :: "r"(addr), "r"(parity) : "memory");
}

// 64-bit SMEM matrix descriptor: SW128, Blackwell, LBO=1, SBO=64
__device__ __forceinline__ uint64_t smem_desc_sw128(uint32_t addr) {
    const uint64_t base =
        (uint64_t(2) << 61) | (uint64_t(1) << 46) |
        (uint64_t(64) << 32) | (uint64_t(1) << 16);
    return base | ((uint64_t)(addr >> 4) & 0x3FFF);
}

__device__ __forceinline__ void mma_tf32_ss(uint32_t d_tmem, uint64_t a_desc,
                                            uint64_t b_desc, uint32_t idesc,
                                            uint32_t enable) {
    asm volatile(
        "{\n .reg .pred p;\n"
        " setp.ne.u32 p, %5, 0;\n"
        " tcgen05.mma.cta_group::1.kind::tf32 [%0], %1, %2, %3, {%4, %4, %4, %4}, p;\n"
        "}"
        :: "r"(d_tmem), "l"(a_desc), "l"(b_desc), "r"(idesc), "r"(0u), "r"(enable)
        : "memory");
}
#else
__device__ __forceinline__ void mma_m16n8k8_tf32(float c[4], const unsigned a[4],
                                                 const unsigned b[2]) {
    asm volatile(
        "mma.sync.aligned.m16n8k8.row.col.f32.tf32.tf32.f32 "
        "{%0,%1,%2,%3}, {%4,%5,%6,%7}, {%8,%9}, {%0,%1,%2,%3};\n"
        : "+f"(c[0]), "+f"(c[1]), "+f"(c[2]), "+f"(c[3])
        : "r"(a[0]), "r"(a[1]), "r"(a[2]), "r"(a[3]), "r"(b[0]), "r"(b[1]));
}
#endif

// ---------------------------------------------------------------------------
// TF32 GEMM: C[m,n] = sum_k A[m,k] * B[n,k]  (both K-contiguous).
// CTA tile 128x128, 256 threads, double-buffered smem pipeline with one
// mbarrier PER STAGE (avoids parity aliasing): chunk c commits to mbar[c&1];
// stage reuse waits on that stage's barrier for its latest issued phase.
// Requires M%128==0, N%128==0, K%64==0, lda/ldb%4==0.
// ---------------------------------------------------------------------------
__global__ void __launch_bounds__(256) tgemm_tc(
    const float* __restrict__ A, const float* __restrict__ B,
    float* __restrict__ C, int K, int lda, int ldb, int ldc)
{
    extern __shared__ unsigned dynbuf[];
#if HAS_TCGEN05
    __shared__ __align__(8) unsigned long long mbar_s[2];
    __shared__ unsigned tptr_s;
#endif

    const int tid = threadIdx.x;
    const int wid = tid >> 5, lane = tid & 31;
    const int bm = blockIdx.y * 128;
    const int bn = blockIdx.x * 128;

    // 1024B-aligned stage base
    uint32_t sbase = smem_u32(dynbuf);
    uint32_t salign = (sbase + 1023u) & ~1023u;
    char* stage_cp = (char*)dynbuf + (salign - sbase);

    // loader mapping: thread covers rows lr + 32*i (i=0..3), float4 col lc
    const int lr = tid >> 3;      // 0..31
    const int lc = tid & 7;       // 0..7  (16B groups within 128B row)

    const float* Ap = A + (size_t)(bm + lr) * lda + lc * 4;
    const float* Bp = B + (size_t)(bn + lr) * ldb + lc * 4;
    const int nch = K / 32;

#if HAS_TCGEN05
    const uint32_t s_mbar0 = smem_u32(&mbar_s[0]);
    const uint32_t s_mbar1 = smem_u32(&mbar_s[1]);
    const uint32_t s_tptr  = smem_u32(&tptr_s);

    // TMEM alloc (warp 0), 128 columns for D
    if (wid == 0) {
        asm volatile("tcgen05.alloc.cta_group::1.sync.aligned.shared::cta.b32 [%0], %1;"
                     :: "r"(s_tptr), "r"(128u) : "memory");
        asm volatile("tcgen05.relinquish_alloc_permit.cta_group::1.sync.aligned;");
    }
    if (tid == 0) { mbar_init(s_mbar0, 1); mbar_init(s_mbar1, 1); }
    __syncthreads();

    uint32_t tmem;
    asm volatile("ld.shared.b32 %0, [%1];" : "=r"(tmem) : "r"(s_tptr));

    // idesc: cfmt=F32(1)@[4:5], afmt=TF32(2)@[7:9], bfmt=TF32(2)@[10:12],
    //        N/8 @[17:22], M/16 @[24:28]
    const uint32_t idesc = (1u << 4) | (2u << 7) | (2u << 10) |
                           ((128u / 8) << 17) | ((128u / 16) << 24);

    // per-barrier phase counters (registers; uniform across threads)
    int ph0 = 0, ph1 = 0;

    // store chunk c into stage st
    auto load_chunk = [&](int c, int st) {
        char* As_c = stage_cp + st * TG_STAGE_BYTES;
        char* Bs_c = As_c + 16384;
#pragma unroll
        for (int i = 0; i < 4; i++) {
            const int row = lr + i * 32;
            float4 av = *(const float4*)(Ap + (size_t)(i * 32) * lda + c * 32);
            float4 bv = *(const float4*)(Bp + (size_t)(i * 32) * ldb + c * 32);
            unsigned off = row * 128 + lc * 16;
            unsigned sw = off ^ ((off >> 3) & 0x70);
            *(uint4*)(As_c + sw) =
                make_uint4(f2tf32(av.x), f2tf32(av.y), f2tf32(av.z), f2tf32(av.w));
            *(uint4*)(Bs_c + sw) =
                make_uint4(f2tf32(bv.x), f2tf32(bv.y), f2tf32(bv.z), f2tf32(bv.w));
        }
    };

    // wait the next phase (in order) of stage barrier b
    auto wait_stage = [&](int b) {
        if (b == 0) { mbar_wait_parity(s_mbar0, (unsigned)(ph0 & 1)); ph0++; }
        else        { mbar_wait_parity(s_mbar1, (unsigned)(ph1 & 1)); ph1++; }
    };

    // preload chunk 0 into stage 0
    load_chunk(0, 0);
    asm volatile("fence.proxy.async.shared::cta;" ::: "memory");
    __syncthreads();

    const bool leader = (wid == 0) && elect_one();

    for (int c = 0; c < nch; c++) {
        const int st = c & 1;
        if (leader) {
            const uint32_t s_a = salign + st * TG_STAGE_BYTES;
            const uint64_t adesc = smem_desc_sw128(s_a);
            const uint64_t bdesc = smem_desc_sw128(s_a + 16384);
#pragma unroll
            for (int ks = 0; ks < 4; ks++) {
                mma_tf32_ss(tmem, adesc + ks * 2, bdesc + ks * 2, idesc,
                            (c > 0 || ks > 0) ? 1u : 0u);
            }
            const uint32_t mb = st ? s_mbar1 : s_mbar0;
            asm volatile(
                "tcgen05.commit.cta_group::1.mbarrier::arrive::one.shared::cluster.b64 [%0];"
                :: "r"(mb) : "memory");
        }
        if (c + 1 < nch) {
            // stage st^1 was last consumed by MMA of chunk c-1 (barrier st^1)
            if (c >= 1) wait_stage(st ^ 1);
            load_chunk(c + 1, st ^ 1);
        }
        asm volatile("fence.proxy.async.shared::cta;" ::: "memory");
        __syncthreads();
    }

    // wait for last chunk's commit (implies ALL prior MMAs done)
    wait_stage((nch - 1) & 1);
    asm volatile("tcgen05.fence::after_thread_sync;" ::: "memory");

    // 8 warps: warps 0-3 -> col groups 0,1; warps 4-7 -> col groups 2,3
    const int row = bm + (wid & 3) * 32 + lane;
    const int g0 = (wid >> 2) * 2;
    float* Crow = C + (size_t)row * ldc + bn;
#pragma unroll
    for (int gg = 0; gg < 2; gg++) {
        const int g = g0 + gg;
        uint32_t d[32];
        asm volatile(
            "tcgen05.ld.sync.aligned.32x32b.x32.b32 "
            "{%0,%1,%2,%3,%4,%5,%6,%7,%8,%9,%10,%11,%12,%13,%14,%15,"
            "%16,%17,%18,%19,%20,%21,%22,%23,%24,%25,%26,%27,%28,%29,%30,%31}, [%32];"
            : "=r"(d[0]), "=r"(d[1]), "=r"(d[2]), "=r"(d[3]),
              "=r"(d[4]), "=r"(d[5]), "=r"(d[6]), "=r"(d[7]),
              "=r"(d[8]), "=r"(d[9]), "=r"(d[10]), "=r"(d[11]),
              "=r"(d[12]), "=r"(d[13]), "=r"(d[14]), "=r"(d[15]),
              "=r"(d[16]), "=r"(d[17]), "=r"(d[18]), "=r"(d[19]),
              "=r"(d[20]), "=r"(d[21]), "=r"(d[22]), "=r"(d[23]),
              "=r"(d[24]), "=r"(d[25]), "=r"(d[26]), "=r"(d[27]),
              "=r"(d[28]), "=r"(d[29]), "=r"(d[30]), "=r"(d[31])
            : "r"(tmem + g * 32));
        asm volatile("tcgen05.wait::ld.sync.aligned;" ::: "memory");
#pragma unroll
        for (int v = 0; v < 8; v++) {
            *(float4*)(Crow + g * 32 + v * 4) = make_float4(
                __uint_as_float(d[v * 4 + 0]), __uint_as_float(d[v * 4 + 1]),
                __uint_as_float(d[v * 4 + 2]), __uint_as_float(d[v * 4 + 3]));
        }
    }

    __syncthreads();
    if (tid == 0) { mbar_inval(s_mbar0); mbar_inval(s_mbar1); }
    __syncthreads();
    if (wid == 0) {
        asm volatile("tcgen05.dealloc.cta_group::1.sync.aligned.b32 %0, %1;"
                     :: "r"(tmem), "r"(128u));
    }
#else
    // ------------------ mma.sync fallback (generic sm_103 pass) ------------
    // 8 warps; warp w covers M rows [w*16, w*16+16), all 128 N columns.
    unsigned* As = (unsigned*)stage_cp;            // [128][32] linear
    unsigned* Bs = (unsigned*)(stage_cp + 16384);  // [128][32] linear

    const int wm = wid * 16;
    const int q = lane & 3;           // 0..3
    const int r = lane >> 2;          // 0..7

    float acc[16][4];
#pragma unroll
    for (int j = 0; j < 16; j++)
#pragma unroll
        for (int t = 0; t < 4; t++) acc[j][t] = 0.f;

    for (int c = 0; c < nch; c++) {
        __syncthreads();
#pragma unroll
        for (int i = 0; i < 4; i++) {
            const int row = lr + i * 32;
            float4 av = *(const float4*)(Ap + (size_t)(i * 32) * lda + c * 32);
            float4 bv = *(const float4*)(Bp + (size_t)(i * 32) * ldb + c * 32);
            *(uint4*)&As[row * 32 + lc * 4] =
                make_uint4(f2tf32(av.x), f2tf32(av.y), f2tf32(av.z), f2tf32(av.w));
            *(uint4*)&Bs[row * 32 + lc * 4] =
                make_uint4(f2tf32(bv.x), f2tf32(bv.y), f2tf32(bv.z), f2tf32(bv.w));
        }
        __syncthreads();

#pragma unroll
        for (int kk = 0; kk < 32; kk += 8) {
            unsigned af[4];
            af[0] = As[(wm + r) * 32 + kk + q];
            af[1] = As[(wm + r + 8) * 32 + kk + q];
            af[2] = As[(wm + r) * 32 + kk + q + 4];
            af[3] = As[(wm + r + 8) * 32 + kk + q + 4];
#pragma unroll
            for (int j = 0; j < 16; j++) {
                unsigned bf[2];
                bf[0] = Bs[(j * 8 + r) * 32 + kk + q];
                bf[1] = Bs[(j * 8 + r) * 32 + kk + q + 4];
                mma_m16n8k8_tf32(acc[j], af, bf);
            }
        }
    }

#pragma unroll
    for (int j = 0; j < 16; j++) {
        const int row = bm + wm + r;
        const int col = bn + j * 8 + q * 2;
        *(float2*)&C[(size_t)row * ldc + col] = make_float2(acc[j][0], acc[j][1]);
        *(float2*)&C[(size_t)(row + 8) * ldc + col] = make_float2(acc[j][2], acc[j][3]);
    }
#endif
}

// ---------------------------------------------------------------------------
// FP32 SGEMM for the small dt-path GEMMs (precision of delta before exp).
// EPI: 0 = plain store, 1 = softplus(x + bias[col]).
// ---------------------------------------------------------------------------
template<int EPI>
__global__ void __launch_bounds__(256, 2) sgemm128(
    const float* __restrict__ A, const float* __restrict__ B,
    float* __restrict__ C, int M, int N, int K,
    int lda, int ldb, int ldc, int kChunk,
    const float* __restrict__ bias)
{
    __shared__ float As[8][128];
    __shared__ float Bs[8][128];

    const int tid = threadIdx.x;
    const int bm = blockIdx.y * 128;
    const int bn = blockIdx.x * 128;
    int kBegin = blockIdx.z * kChunk;
    int kEnd   = kBegin + kChunk; if (kEnd > K) kEnd = K;
    C += (size_t)blockIdx.z * (size_t)M * (size_t)ldc;

    const int ar = tid >> 1;
    const int ac = (tid & 1) * 4;
    const int ty = tid >> 4;
    const int tx = tid & 15;

    float acc[8][8];
#pragma unroll
    for (int i = 0; i < 8; i++)
#pragma unroll
        for (int j = 0; j < 8; j++) acc[i][j] = 0.f;

    const float* Aptr = A + (size_t)(bm + ar) * lda + ac;
    const int brow = bn + ar;
    const float* Bptr = B + (size_t)brow * ldb + ac;
    const bool bvalid = (brow < N);

    for (int k0 = kBegin; k0 < kEnd; k0 += 8) {
        float4 av = *(const float4*)(Aptr + k0);
        float4 bv = make_float4(0.f, 0.f, 0.f, 0.f);
        if (bvalid) bv = *(const float4*)(Bptr + k0);

        __syncthreads();
        As[ac + 0][ar] = av.x; As[ac + 1][ar] = av.y;
        As[ac + 2][ar] = av.z; As[ac + 3][ar] = av.w;
        Bs[ac + 0][ar] = bv.x; Bs[ac + 1][ar] = bv.y;
        Bs[ac + 2][ar] = bv.z; Bs[ac + 3][ar] = bv.w;
        __syncthreads();

#pragma unroll
        for (int kk = 0; kk < 8; kk++) {
            float a[8], b[8];
#pragma unroll
            for (int i = 0; i < 8; i++) a[i] = As[kk][ty * 8 + i];
#pragma unroll
            for (int j = 0; j < 8; j++) b[j] = Bs[kk][tx * 8 + j];
#pragma unroll
            for (int i = 0; i < 8; i++)
#pragma unroll
                for (int j = 0; j < 8; j++)
                    acc[i][j] = fmaf(a[i], b[j], acc[i][j]);
        }
    }

#pragma unroll
    for (int i = 0; i < 8; i++) {
        const int row = bm + ty * 8 + i;
#pragma unroll
        for (int j = 0; j < 8; j++) {
            const int col = bn + tx * 8 + j;
            if (col < N) {
                float v = acc[i][j];
                if (EPI == 1) {
                    v += bias[col];
                    v = fmaxf(v, 0.f) + log1pf(__expf(-fabsf(v)));
                }
                C[(size_t)row * ldc + col] = v;
            }
        }
    }
}

// ---------------------------------------------------------------------------
// Depthwise causal conv (k=4) + bias + SiLU
// ---------------------------------------------------------------------------
__global__ void conv_silu_kernel(const float* __restrict__ xz,
                                 const float* __restrict__ cw,
                                 const float* __restrict__ cb,
                                 float* __restrict__ xsc)
{
    const int idx = blockIdx.x * blockDim.x + threadIdx.x;
    if (idx >= MROWS * DINNER) return;
    const int d = idx & (DINNER - 1);
    const int m = idx >> 11;
    const int l = m & (LSEQ - 1);

    const float w0 = cw[d * 4 + 0], w1 = cw[d * 4 + 1];
    const float w2 = cw[d * 4 + 2], w3 = cw[d * 4 + 3];
    const float* p = xz + (size_t)m * NXZ + d;

    float acc = cb[d] + w3 * p[0];
    if (l >= 1) acc = fmaf(w2, p[-NXZ],     acc);
    if (l >= 2) acc = fmaf(w1, p[-2 * NXZ], acc);
    if (l >= 3) acc = fmaf(w0, p[-3 * NXZ], acc);

    xsc[idx] = acc / (1.f + __expf(-acc));
}

// ---------------------------------------------------------------------------
// Split-K reduction for x_proj
// ---------------------------------------------------------------------------
__global__ void reduce_dbc_kernel(const float* __restrict__ part,
                                  float* __restrict__ out)
{
    const int idx = blockIdx.x * blockDim.x + threadIdx.x;
    if (idx >= MROWS * NDBC) return;
    float s = 0.f;
#pragma unroll
    for (int j = 0; j < SPLITK_XPROJ; j++)
        s += part[(size_t)j * MROWS * NDBC + idx];
    out[idx] = s;
}

// ---------------------------------------------------------------------------
// Selective scan: 16 lanes per (b,d) channel, one lane per state n.
// ---------------------------------------------------------------------------
__global__ void scan_kernel(const float* __restrict__ delta,
                            const float* __restrict__ xsc,
                            const float* __restrict__ dbc,
                            const float* __restrict__ xz,
                            const float* __restrict__ A_log,
                            const float* __restrict__ Dp,
                            float* __restrict__ y)
{
    const int gt = blockIdx.x * blockDim.x + threadIdx.x;
    const int ch = gt >> 4;
    if (ch >= BSZ * DINNER) return;
    const int n = threadIdx.x & 15;
    const int b = ch >> 11;
    const int d = ch & (DINNER - 1);

    const float An = -__expf(A_log[d * DSTATE + n]);
    const float Dd = Dp[d];

    const float* drow  = delta + (size_t)b * LSEQ * DINNER + d;
    const float* xrow  = xsc   + (size_t)b * LSEQ * DINNER + d;
    const float* zrow  = xz    + (size_t)b * LSEQ * NXZ + DINNER + d;
    const float* bcrow = dbc   + (size_t)b * LSEQ * NDBC;
    float*       yrow  = y     + (size_t)b * LSEQ * DINNER + d;

    float h = 0.f;
    for (int l = 0; l < LSEQ; l++) {
        const float dl = drow[(size_t)l * DINNER];
        const float xv = xrow[(size_t)l * DINNER];
        const float Bv = bcrow[l * NDBC + DTRANK + n];
        const float Cv = bcrow[l * NDBC + DTRANK + DSTATE + n];

        const float dA = __expf(dl * An);
        h = fmaf(dA, h, dl * xv * Bv);

        float part = h * Cv;
        part += __shfl_xor_sync(0xffffffffu, part, 8, 16);
        part += __shfl_xor_sync(0xffffffffu, part, 4, 16);
        part += __shfl_xor_sync(0xffffffffu, part, 2, 16);
        part += __shfl_xor_sync(0xffffffffu, part, 1, 16);

        if (n == 0) {
            const float yv = part + Dd * xv;
            const float zv = zrow[(size_t)l * NXZ];
            const float sz = zv / (1.f + __expf(-zv));
            yrow[(size_t)l * DINNER] = yv * sz;
        }
    }
}

// ---------------------------------------------------------------------------
// Launch
// ---------------------------------------------------------------------------
extern "C" void kernel_launch(void* const* d_in, const int* in_sizes, int n_in,
                              void* d_out, int out_size)
{
    const float* x         = (const float*)d_in[0];
    const float* in_proj_w = (const float*)d_in[1];
    const float* conv_w    = (const float*)d_in[2];
    const float* conv_b    = (const float*)d_in[3];
    const float* x_proj_w  = (const float*)d_in[4];
    const float* dt_proj_w = (const float*)d_in[5];
    const float* dt_proj_b = (const float*)d_in[6];
    const float* A_log     = (const float*)d_in[7];
    const float* Dvec      = (const float*)d_in[8];
    const float* out_proj_w= (const float*)d_in[9];
    float* out = (float*)d_out;

    float *xz, *xsc, *dbc_part, *dbc, *delta, *yb;
    cudaGetSymbolAddress((void**)&xz,       g_xz);
    cudaGetSymbolAddress((void**)&xsc,      g_xsc);
    cudaGetSymbolAddress((void**)&dbc_part, g_dbc_part);
    cudaGetSymbolAddress((void**)&dbc,      g_dbc);
    cudaGetSymbolAddress((void**)&delta,    g_delta);
    cudaGetSymbolAddress((void**)&yb,       g_y);

    cudaFuncSetAttribute(tgemm_tc, cudaFuncAttributeMaxDynamicSharedMemorySize,
                         TG_SMEM_BYTES);

    // 1) xz = x @ in_proj_w^T  (2048 x 4096, K=1024)  — tcgen05 TF32, pipelined
    {
        dim3 grid(NXZ / 128, MROWS / 128);
        tgemm_tc<<<grid, 256, TG_SMEM_BYTES>>>(x, in_proj_w, xz,
                                               DMODEL, DMODEL, DMODEL, NXZ);
    }

    // 2) depthwise conv + bias + silu -> xsc
    {
        int n = MROWS * DINNER;
        conv_silu_kernel<<<(n + 255) / 256, 256>>>(xz, conv_w, conv_b, xsc);
    }

    // 3) dbc = xsc @ x_proj_w^T  (2048 x 96, K=2048), fp32, split-K=8
    {
        dim3 grid(1, MROWS / 128, SPLITK_XPROJ);
        sgemm128<0><<<grid, 256>>>(xsc, x_proj_w, dbc_part,
                                   MROWS, NDBC, DINNER,
                                   DINNER, DINNER, NDBC, DINNER / SPLITK_XPROJ,
                                   nullptr);
        int n = MROWS * NDBC;
        reduce_dbc_kernel<<<(n + 255) / 256, 256>>>(dbc_part, dbc);
    }

    // 4) delta = softplus(dbc[:, :64] @ dt_proj_w^T + dt_proj_b)  fp32
    {
        dim3 grid(DINNER / 128, MROWS / 128, 1);
        sgemm128<1><<<grid, 256>>>(dbc, dt_proj_w, delta,
                                   MROWS, DINNER, DTRANK,
                                   NDBC, DTRANK, DINNER, DTRANK, dt_proj_b);
    }

    // 5) selective scan -> yb
    {
        int threads = BSZ * DINNER * DSTATE;
        scan_kernel<<<threads / 256, 256>>>(delta, xsc, dbc, xz, A_log, Dvec, yb);
    }

    // 6) out = yb @ out_proj_w^T  (2048 x 1024, K=2048) — tcgen05 TF32, pipelined
    {
        dim3 grid(DMODEL / 128, MROWS / 128);
        tgemm_tc<<<grid, 256, TG_SMEM_BYTES>>>(yb, out_proj_w, out,
                                               DINNER, DINNER, DINNER, DMODEL);
    }
}

// round 9
// speedup vs baseline: 1.0898x; 1.0898x over previous
#include <cuda_runtime.h>
#include <cuda_bf16.h>
#include <math.h>
#include <stdint.h>

// ---------------------------------------------------------------------------
// Problem constants
// ---------------------------------------------------------------------------
#define BSZ     2
#define LSEQ    1024
#define DMODEL  1024
#define DINNER  2048
#define DSTATE  16
#define DTRANK  64
#define MROWS   (BSZ * LSEQ)        // 2048
#define NXZ     (2 * DINNER)        // 4096
#define NDBC    (DTRANK + 2*DSTATE) // 96
#define SPLITK_XPROJ 8

// tcgen05 is only legal on arch-specific ("a") targets. The harness also
// compiles a plain compute_103/sm_103 pass; give that pass an mma.sync path.
#if defined(__CUDA_ARCH_FEAT_SM103_ALL) || defined(__CUDA_ARCH_FEAT_SM100_ALL) || defined(__CUDA_ARCH_FEAT_SM101_ALL)
#define HAS_TCGEN05 1
#else
#define HAS_TCGEN05 0
#endif

// ---------------------------------------------------------------------------
// Scratch (static device memory; no allocations allowed)
// ---------------------------------------------------------------------------
__device__ float    g_xz[MROWS * NXZ];                       // (xs | z)
__device__ float    g_xsc[MROWS * DINNER];                   // conv+silu output
__device__ float    g_dbc_part[SPLITK_XPROJ * MROWS * NDBC];
__device__ float    g_dbc[MROWS * NDBC];
__device__ float    g_delta[MROWS * DINNER];
__device__ unsigned g_xt[MROWS * DMODEL];                    // x in tf32
__device__ unsigned g_wt_in[NXZ * DMODEL];                   // in_proj_w tf32
__device__ unsigned g_wt_out[DMODEL * DINNER];               // out_proj_w tf32
__device__ unsigned g_yt[MROWS * DINNER];                    // scan output tf32

// ---------------------------------------------------------------------------
// Small PTX helpers
// ---------------------------------------------------------------------------
__device__ __forceinline__ unsigned f2tf32(float x) {
    unsigned r;
    asm("cvt.rna.tf32.f32 %0, %1;" : "=r"(r) : "f"(x));
    return r;
}

__device__ __forceinline__ uint32_t smem_u32(const void* p) {
    uint32_t a;
    asm("{ .reg .u64 t; cvta.to.shared.u64 t, %1; cvt.u32.u64 %0, t; }"
        : "=r"(a) : "l"(p));
    return a;
}

__device__ __forceinline__ void cp_async16(uint32_t smem_addr, const void* gptr) {
    asm volatile("cp.async.cg.shared.global [%0], [%1], 16;"
                 :: "r"(smem_addr), "l"(gptr) : "memory");
}
__device__ __forceinline__ void cp_async_commit() {
    asm volatile("cp.async.commit_group;" ::: "memory");
}
__device__ __forceinline__ void cp_async_wait_all() {
    asm volatile("cp.async.wait_group 0;" ::: "memory");
}

#if HAS_TCGEN05
__device__ __forceinline__ uint32_t elect_one() {
    uint32_t pred;
    asm volatile("{\n .reg .pred p;\n elect.sync _|p, 0xFFFFFFFF;\n"
                 " selp.b32 %0, 1, 0, p;\n}" : "=r"(pred));
    return pred;
}

__device__ __forceinline__ void mbar_init(uint32_t addr, uint32_t cnt) {
    asm volatile("mbarrier.init.shared.b64 [%0], %1;" :: "r"(addr), "r"(cnt) : "memory");
}
__device__ __forceinline__ void mbar_inval(uint32_t addr) {
    asm volatile("mbarrier.inval.shared.b64 [%0];" :: "r"(addr) : "memory");
}
__device__ __forceinline__ void mbar_wait_parity(uint32_t addr, uint32_t parity) {
    asm volatile(
        "{\n .reg .pred P;\n"
        "WAIT_%=:\n"
        " mbarrier.try_wait.parity.acquire.cta.shared::cta.b64 P, [%0], %1, 0x989680;\n"
        " @P bra.uni DONE_%=;\n"
        " bra.uni WAIT_%=;\n"
        "DONE_%=:\n}"
        :: "r"(addr), "r"(parity) : "memory");
}

// 64-bit SMEM matrix descriptor: SW128, Blackwell, LBO=1, SBO=64
__device__ __forceinline__ uint64_t smem_desc_sw128(uint32_t addr) {
    const uint64_t base =
        (uint64_t(2) << 61) | (uint64_t(1) << 46) |
        (uint64_t(64) << 32) | (uint64_t(1) << 16);
    return base | ((uint64_t)(addr >> 4) & 0x3FFF);
}

__device__ __forceinline__ void mma_tf32_ss(uint32_t d_tmem, uint64_t a_desc,
                                            uint64_t b_desc, uint32_t idesc,
                                            uint32_t enable) {
    asm volatile(
        "{\n .reg .pred p;\n"
        " setp.ne.u32 p, %5, 0;\n"
        " tcgen05.mma.cta_group::1.kind::tf32 [%0], %1, %2, %3, {%4, %4, %4, %4}, p;\n"
        "}"
        :: "r"(d_tmem), "l"(a_desc), "l"(b_desc), "r"(idesc), "r"(0u), "r"(enable)
        : "memory");
}
#else
__device__ __forceinline__ void mma_m16n8k8_tf32(float c[4], const unsigned a[4],
                                                 const unsigned b[2]) {
    asm volatile(
        "mma.sync.aligned.m16n8k8.row.col.f32.tf32.tf32.f32 "
        "{%0,%1,%2,%3}, {%4,%5,%6,%7}, {%8,%9}, {%0,%1,%2,%3};\n"
        : "+f"(c[0]), "+f"(c[1]), "+f"(c[2]), "+f"(c[3])
        : "r"(a[0]), "r"(a[1]), "r"(a[2]), "r"(a[3]), "r"(b[0]), "r"(b[1]));
}
#endif

// ---------------------------------------------------------------------------
// Elementwise fp32 -> tf32(rna) conversion (vectorized)
// ---------------------------------------------------------------------------
__global__ void cvt_tf32_kernel(const float4* __restrict__ in,
                                uint4* __restrict__ out, int n4)
{
    const int i = blockIdx.x * blockDim.x + threadIdx.x;
    if (i >= n4) return;
    float4 v = in[i];
    out[i] = make_uint4(f2tf32(v.x), f2tf32(v.y), f2tf32(v.z), f2tf32(v.w));
}

// ---------------------------------------------------------------------------
// TF32 tensor GEMM on PRE-CONVERTED tf32 inputs:
// C[m,n] = sum_k A[m,k]*B[n,k]. CTA tile 128x128, 128 threads, single-stage
// smem (32KB) loaded with cp.async (no cvt, no register transit).
// Requires M%128==0, N%128==0, K%32==0, lda/ldb%4==0.
// ---------------------------------------------------------------------------
__global__ void __launch_bounds__(128, 4) tgemm_tc(
    const unsigned* __restrict__ A, const unsigned* __restrict__ B,
    float* __restrict__ C, int K, int lda, int ldb, int ldc)
{
    __shared__ __align__(1024) unsigned As[128 * 32];   // 16 KB
    __shared__ __align__(1024) unsigned Bs[128 * 32];   // 16 KB
#if HAS_TCGEN05
    __shared__ __align__(8) unsigned long long mbar_s;
    __shared__ unsigned tptr_s;
#endif

    const int tid = threadIdx.x;
    const int wid = tid >> 5, lane = tid & 31;
    const int bm = blockIdx.y * 128;
    const int bn = blockIdx.x * 128;

    // loader mapping: thread covers rows r0 + 16*i (i=0..7), 16B column c4
    const int r0 = tid >> 3;      // 0..15
    const int c4 = tid & 7;       // 0..7

    const unsigned* Ap = A + (size_t)(bm + r0) * lda + c4 * 4;
    const unsigned* Bp = B + (size_t)(bn + r0) * ldb + c4 * 4;
    const int nch = K / 32;

    const uint32_t s_as = smem_u32(As);
    const uint32_t s_bs = smem_u32(Bs);

#if HAS_TCGEN05
    const uint32_t s_mbar = smem_u32(&mbar_s);
    const uint32_t s_tptr = smem_u32(&tptr_s);

    if (wid == 0) {
        asm volatile("tcgen05.alloc.cta_group::1.sync.aligned.shared::cta.b32 [%0], %1;"
                     :: "r"(s_tptr), "r"(128u) : "memory");
        asm volatile("tcgen05.relinquish_alloc_permit.cta_group::1.sync.aligned;");
    }
    if (tid == 0) mbar_init(s_mbar, 1);
    __syncthreads();

    uint32_t tmem;
    asm volatile("ld.shared.b32 %0, [%1];" : "=r"(tmem) : "r"(s_tptr));

    // idesc: cfmt=F32(1)@[4:5], afmt=TF32(2)@[7:9], bfmt=TF32(2)@[10:12],
    //        N/8 @[17:22], M/16 @[24:28]
    const uint32_t idesc = (1u << 4) | (2u << 7) | (2u << 10) |
                           ((128u / 8) << 17) | ((128u / 16) << 24);

    const uint64_t adesc0 = smem_desc_sw128(s_as);
    const uint64_t bdesc0 = smem_desc_sw128(s_bs);
    const bool leader = (wid == 0) && elect_one();

    for (int c = 0; c < nch; c++) {
        if (c > 0) mbar_wait_parity(s_mbar, (c - 1) & 1); // MMA done reading smem

#pragma unroll
        for (int i = 0; i < 8; i++) {
            const int row = r0 + i * 16;
            unsigned off = row * 128 + c4 * 16;
            unsigned sw = off ^ ((off >> 3) & 0x70);
            cp_async16(s_as + sw, Ap + (size_t)(i * 16) * lda + c * 32);
            cp_async16(s_bs + sw, Bp + (size_t)(i * 16) * ldb + c * 32);
        }
        cp_async_commit();
        cp_async_wait_all();
        asm volatile("fence.proxy.async.shared::cta;" ::: "memory");
        __syncthreads();

        if (leader) {
#pragma unroll
            for (int ks = 0; ks < 4; ks++) {
                mma_tf32_ss(tmem, adesc0 + ks * 2, bdesc0 + ks * 2, idesc,
                            (c > 0 || ks > 0) ? 1u : 0u);
            }
            asm volatile(
                "tcgen05.commit.cta_group::1.mbarrier::arrive::one.shared::cluster.b64 [%0];"
                :: "r"(s_mbar) : "memory");
        }
    }

    // wait for last chunk's MMA, then read D from TMEM
    mbar_wait_parity(s_mbar, (nch - 1) & 1);
    asm volatile("tcgen05.fence::after_thread_sync;" ::: "memory");

    const int row = bm + wid * 32 + lane;
    float* Crow = C + (size_t)row * ldc + bn;
#pragma unroll
    for (int g = 0; g < 4; g++) {
        uint32_t d[32];
        asm volatile(
            "tcgen05.ld.sync.aligned.32x32b.x32.b32 "
            "{%0,%1,%2,%3,%4,%5,%6,%7,%8,%9,%10,%11,%12,%13,%14,%15,"
            "%16,%17,%18,%19,%20,%21,%22,%23,%24,%25,%26,%27,%28,%29,%30,%31}, [%32];"
            : "=r"(d[0]), "=r"(d[1]), "=r"(d[2]), "=r"(d[3]),
              "=r"(d[4]), "=r"(d[5]), "=r"(d[6]), "=r"(d[7]),
              "=r"(d[8]), "=r"(d[9]), "=r"(d[10]), "=r"(d[11]),
              "=r"(d[12]), "=r"(d[13]), "=r"(d[14]), "=r"(d[15]),
              "=r"(d[16]), "=r"(d[17]), "=r"(d[18]), "=r"(d[19]),
              "=r"(d[20]), "=r"(d[21]), "=r"(d[22]), "=r"(d[23]),
              "=r"(d[24]), "=r"(d[25]), "=r"(d[26]), "=r"(d[27]),
              "=r"(d[28]), "=r"(d[29]), "=r"(d[30]), "=r"(d[31])
            : "r"(tmem + g * 32));
        asm volatile("tcgen05.wait::ld.sync.aligned;" ::: "memory");
#pragma unroll
        for (int v = 0; v < 8; v++) {
            *(float4*)(Crow + g * 32 + v * 4) = make_float4(
                __uint_as_float(d[v * 4 + 0]), __uint_as_float(d[v * 4 + 1]),
                __uint_as_float(d[v * 4 + 2]), __uint_as_float(d[v * 4 + 3]));
        }
    }

    __syncthreads();
    if (tid == 0) mbar_inval(s_mbar);
    __syncthreads();
    if (wid == 0) {
        asm volatile("tcgen05.dealloc.cta_group::1.sync.aligned.b32 %0, %1;"
                     :: "r"(tmem), "r"(128u));
    }
#else
    // ------------------ mma.sync fallback (generic sm_103 pass) ------------
    // 4 warps; warp w covers M rows [w*32, w*32+32), all 128 N columns.
    const int wm = wid * 32;
    const int q = lane & 3;
    const int r = lane >> 2;

    float acc[2][16][4];
#pragma unroll
    for (int i = 0; i < 2; i++)
#pragma unroll
        for (int j = 0; j < 16; j++)
#pragma unroll
            for (int t = 0; t < 4; t++) acc[i][j][t] = 0.f;

    for (int c = 0; c < nch; c++) {
        __syncthreads();
#pragma unroll
        for (int i = 0; i < 8; i++) {
            const int row = r0 + i * 16;
            uint4 av = *(const uint4*)(Ap + (size_t)(i * 16) * lda + c * 32);
            uint4 bv = *(const uint4*)(Bp + (size_t)(i * 16) * ldb + c * 32);
            *(uint4*)&As[row * 32 + c4 * 4] = av;
            *(uint4*)&Bs[row * 32 + c4 * 4] = bv;
        }
        __syncthreads();

#pragma unroll
        for (int kk = 0; kk < 32; kk += 8) {
            unsigned af[2][4];
#pragma unroll
            for (int i = 0; i < 2; i++) {
                const int mrow = wm + i * 16;
                af[i][0] = As[(mrow + r) * 32 + kk + q];
                af[i][1] = As[(mrow + r + 8) * 32 + kk + q];
                af[i][2] = As[(mrow + r) * 32 + kk + q + 4];
                af[i][3] = As[(mrow + r + 8) * 32 + kk + q + 4];
            }
#pragma unroll
            for (int j = 0; j < 16; j++) {
                unsigned bf[2];
                bf[0] = Bs[(j * 8 + r) * 32 + kk + q];
                bf[1] = Bs[(j * 8 + r) * 32 + kk + q + 4];
#pragma unroll
                for (int i = 0; i < 2; i++)
                    mma_m16n8k8_tf32(acc[i][j], af[i], bf);
            }
        }
    }

#pragma unroll
    for (int i = 0; i < 2; i++) {
        const int row = bm + wm + i * 16 + r;
#pragma unroll
        for (int j = 0; j < 16; j++) {
            const int col = bn + j * 8 + q * 2;
            *(float2*)&C[(size_t)row * ldc + col] =
                make_float2(acc[i][j][0], acc[i][j][1]);
            *(float2*)&C[(size_t)(row + 8) * ldc + col] =
                make_float2(acc[i][j][2], acc[i][j][3]);
        }
    }
#endif
}

// ---------------------------------------------------------------------------
// FP32 SGEMM for the small dt-path GEMMs (precision of delta before exp).
// EPI: 0 = plain store, 1 = softplus(x + bias[col]).
// ---------------------------------------------------------------------------
template<int EPI>
__global__ void __launch_bounds__(256, 2) sgemm128(
    const float* __restrict__ A, const float* __restrict__ B,
    float* __restrict__ C, int M, int N, int K,
    int lda, int ldb, int ldc, int kChunk,
    const float* __restrict__ bias)
{
    __shared__ float As[8][128];
    __shared__ float Bs[8][128];

    const int tid = threadIdx.x;
    const int bm = blockIdx.y * 128;
    const int bn = blockIdx.x * 128;
    int kBegin = blockIdx.z * kChunk;
    int kEnd   = kBegin + kChunk; if (kEnd > K) kEnd = K;
    C += (size_t)blockIdx.z * (size_t)M * (size_t)ldc;

    const int ar = tid >> 1;
    const int ac = (tid & 1) * 4;
    const int ty = tid >> 4;
    const int tx = tid & 15;

    float acc[8][8];
#pragma unroll
    for (int i = 0; i < 8; i++)
#pragma unroll
        for (int j = 0; j < 8; j++) acc[i][j] = 0.f;

    const float* Aptr = A + (size_t)(bm + ar) * lda + ac;
    const int brow = bn + ar;
    const float* Bptr = B + (size_t)brow * ldb + ac;
    const bool bvalid = (brow < N);

    for (int k0 = kBegin; k0 < kEnd; k0 += 8) {
        float4 av = *(const float4*)(Aptr + k0);
        float4 bv = make_float4(0.f, 0.f, 0.f, 0.f);
        if (bvalid) bv = *(const float4*)(Bptr + k0);

        __syncthreads();
        As[ac + 0][ar] = av.x; As[ac + 1][ar] = av.y;
        As[ac + 2][ar] = av.z; As[ac + 3][ar] = av.w;
        Bs[ac + 0][ar] = bv.x; Bs[ac + 1][ar] = bv.y;
        Bs[ac + 2][ar] = bv.z; Bs[ac + 3][ar] = bv.w;
        __syncthreads();

#pragma unroll
        for (int kk = 0; kk < 8; kk++) {
            float a[8], b[8];
#pragma unroll
            for (int i = 0; i < 8; i++) a[i] = As[kk][ty * 8 + i];
#pragma unroll
            for (int j = 0; j < 8; j++) b[j] = Bs[kk][tx * 8 + j];
#pragma unroll
            for (int i = 0; i < 8; i++)
#pragma unroll
                for (int j = 0; j < 8; j++)
                    acc[i][j] = fmaf(a[i], b[j], acc[i][j]);
        }
    }

#pragma unroll
    for (int i = 0; i < 8; i++) {
        const int row = bm + ty * 8 + i;
#pragma unroll
        for (int j = 0; j < 8; j++) {
            const int col = bn + tx * 8 + j;
            if (col < N) {
                float v = acc[i][j];
                if (EPI == 1) {
                    v += bias[col];
                    v = fmaxf(v, 0.f) + log1pf(__expf(-fabsf(v)));
                }
                C[(size_t)row * ldc + col] = v;
            }
        }
    }
}

// ---------------------------------------------------------------------------
// Depthwise causal conv (k=4) + bias + SiLU
// ---------------------------------------------------------------------------
__global__ void conv_silu_kernel(const float* __restrict__ xz,
                                 const float* __restrict__ cw,
                                 const float* __restrict__ cb,
                                 float* __restrict__ xsc)
{
    const int idx = blockIdx.x * blockDim.x + threadIdx.x;
    if (idx >= MROWS * DINNER) return;
    const int d = idx & (DINNER - 1);
    const int m = idx >> 11;
    const int l = m & (LSEQ - 1);

    const float w0 = cw[d * 4 + 0], w1 = cw[d * 4 + 1];
    const float w2 = cw[d * 4 + 2], w3 = cw[d * 4 + 3];
    const float* p = xz + (size_t)m * NXZ + d;

    float acc = cb[d] + w3 * p[0];
    if (l >= 1) acc = fmaf(w2, p[-NXZ],     acc);
    if (l >= 2) acc = fmaf(w1, p[-2 * NXZ], acc);
    if (l >= 3) acc = fmaf(w0, p[-3 * NXZ], acc);

    xsc[idx] = acc / (1.f + __expf(-acc));
}

// ---------------------------------------------------------------------------
// Split-K reduction for x_proj
// ---------------------------------------------------------------------------
__global__ void reduce_dbc_kernel(const float* __restrict__ part,
                                  float* __restrict__ out)
{
    const int idx = blockIdx.x * blockDim.x + threadIdx.x;
    if (idx >= MROWS * NDBC) return;
    float s = 0.f;
#pragma unroll
    for (int j = 0; j < SPLITK_XPROJ; j++)
        s += part[(size_t)j * MROWS * NDBC + idx];
    out[idx] = s;
}

// ---------------------------------------------------------------------------
// Selective scan: 16 lanes per (b,d) channel, one lane per state n.
// Writes gated output PRE-CONVERTED to tf32 for the out_proj GEMM.
// ---------------------------------------------------------------------------
__global__ void scan_kernel(const float* __restrict__ delta,
                            const float* __restrict__ xsc,
                            const float* __restrict__ dbc,
                            const float* __restrict__ xz,
                            const float* __restrict__ A_log,
                            const float* __restrict__ Dp,
                            unsigned* __restrict__ yt)
{
    const int gt = blockIdx.x * blockDim.x + threadIdx.x;
    const int ch = gt >> 4;
    if (ch >= BSZ * DINNER) return;
    const int n = threadIdx.x & 15;
    const int b = ch >> 11;
    const int d = ch & (DINNER - 1);

    const float An = -__expf(A_log[d * DSTATE + n]);
    const float Dd = Dp[d];

    const float* drow  = delta + (size_t)b * LSEQ * DINNER + d;
    const float* xrow  = xsc   + (size_t)b * LSEQ * DINNER + d;
    const float* zrow  = xz    + (size_t)b * LSEQ * NXZ + DINNER + d;
    const float* bcrow = dbc   + (size_t)b * LSEQ * NDBC;
    unsigned*    yrow  = yt    + (size_t)b * LSEQ * DINNER + d;

    float h = 0.f;
    for (int l = 0; l < LSEQ; l++) {
        const float dl = drow[(size_t)l * DINNER];
        const float xv = xrow[(size_t)l * DINNER];
        const float Bv = bcrow[l * NDBC + DTRANK + n];
        const float Cv = bcrow[l * NDBC + DTRANK + DSTATE + n];

        const float dA = __expf(dl * An);
        h = fmaf(dA, h, dl * xv * Bv);

        float part = h * Cv;
        part += __shfl_xor_sync(0xffffffffu, part, 8, 16);
        part += __shfl_xor_sync(0xffffffffu, part, 4, 16);
        part += __shfl_xor_sync(0xffffffffu, part, 2, 16);
        part += __shfl_xor_sync(0xffffffffu, part, 1, 16);

        if (n == 0) {
            const float yv = part + Dd * xv;
            const float zv = zrow[(size_t)l * NXZ];
            const float sz = zv / (1.f + __expf(-zv));
            yrow[(size_t)l * DINNER] = f2tf32(yv * sz);
        }
    }
}

// ---------------------------------------------------------------------------
// Launch
// ---------------------------------------------------------------------------
extern "C" void kernel_launch(void* const* d_in, const int* in_sizes, int n_in,
                              void* d_out, int out_size)
{
    const float* x         = (const float*)d_in[0];
    const float* in_proj_w = (const float*)d_in[1];
    const float* conv_w    = (const float*)d_in[2];
    const float* conv_b    = (const float*)d_in[3];
    const float* x_proj_w  = (const float*)d_in[4];
    const float* dt_proj_w = (const float*)d_in[5];
    const float* dt_proj_b = (const float*)d_in[6];
    const float* A_log     = (const float*)d_in[7];
    const float* Dvec      = (const float*)d_in[8];
    const float* out_proj_w= (const float*)d_in[9];
    float* out = (float*)d_out;

    float *xz, *xsc, *dbc_part, *dbc, *delta;
    unsigned *xt, *wt_in, *wt_out, *yt;
    cudaGetSymbolAddress((void**)&xz,       g_xz);
    cudaGetSymbolAddress((void**)&xsc,      g_xsc);
    cudaGetSymbolAddress((void**)&dbc_part, g_dbc_part);
    cudaGetSymbolAddress((void**)&dbc,      g_dbc);
    cudaGetSymbolAddress((void**)&delta,    g_delta);
    cudaGetSymbolAddress((void**)&xt,       g_xt);
    cudaGetSymbolAddress((void**)&wt_in,    g_wt_in);
    cudaGetSymbolAddress((void**)&wt_out,   g_wt_out);
    cudaGetSymbolAddress((void**)&yt,       g_yt);

    // 0) pre-convert fp32 -> tf32 (once per call)
    {
        int n4;
        n4 = (MROWS * DMODEL) / 4;
        cvt_tf32_kernel<<<(n4 + 255) / 256, 256>>>((const float4*)x, (uint4*)xt, n4);
        n4 = (NXZ * DMODEL) / 4;
        cvt_tf32_kernel<<<(n4 + 255) / 256, 256>>>((const float4*)in_proj_w, (uint4*)wt_in, n4);
        n4 = (DMODEL * DINNER) / 4;
        cvt_tf32_kernel<<<(n4 + 255) / 256, 256>>>((const float4*)out_proj_w, (uint4*)wt_out, n4);
    }

    // 1) xz = x @ in_proj_w^T  (2048 x 4096, K=1024)  — tcgen05 TF32
    {
        dim3 grid(NXZ / 128, MROWS / 128);
        tgemm_tc<<<grid, 128>>>(xt, wt_in, xz, DMODEL, DMODEL, DMODEL, NXZ);
    }

    // 2) depthwise conv + bias + silu -> xsc
    {
        int n = MROWS * DINNER;
        conv_silu_kernel<<<(n + 255) / 256, 256>>>(xz, conv_w, conv_b, xsc);
    }

    // 3) dbc = xsc @ x_proj_w^T  (2048 x 96, K=2048), fp32, split-K=8
    {
        dim3 grid(1, MROWS / 128, SPLITK_XPROJ);
        sgemm128<0><<<grid, 256>>>(xsc, x_proj_w, dbc_part,
                                   MROWS, NDBC, DINNER,
                                   DINNER, DINNER, NDBC, DINNER / SPLITK_XPROJ,
                                   nullptr);
        int n = MROWS * NDBC;
        reduce_dbc_kernel<<<(n + 255) / 256, 256>>>(dbc_part, dbc);
    }

    // 4) delta = softplus(dbc[:, :64] @ dt_proj_w^T + dt_proj_b)  fp32
    {
        dim3 grid(DINNER / 128, MROWS / 128, 1);
        sgemm128<1><<<grid, 256>>>(dbc, dt_proj_w, delta,
                                   MROWS, DINNER, DTRANK,
                                   NDBC, DTRANK, DINNER, DTRANK, dt_proj_b);
    }

    // 5) selective scan -> yt (tf32)
    {
        int threads = BSZ * DINNER * DSTATE;
        scan_kernel<<<threads / 256, 256>>>(delta, xsc, dbc, xz, A_log, Dvec, yt);
    }

    // 6) out = y @ out_proj_w^T  (2048 x 1024, K=2048) — tcgen05 TF32
    {
        dim3 grid(DMODEL / 128, MROWS / 128);
        tgemm_tc<<<grid, 128>>>(yt, wt_out, out, DINNER, DINNER, DINNER, DMODEL);
    }
}

// round 10
// speedup vs baseline: 2.5113x; 2.3045x over previous
#include <cuda_runtime.h>
#include <cuda_bf16.h>
#include <math.h>
#include <stdint.h>

// ---------------------------------------------------------------------------
// Problem constants
// ---------------------------------------------------------------------------
#define BSZ     2
#define LSEQ    1024
#define DMODEL  1024
#define DINNER  2048
#define DSTATE  16
#define DTRANK  64
#define MROWS   (BSZ * LSEQ)        // 2048
#define NXZ     (2 * DINNER)        // 4096
#define NDBC    (DTRANK + 2*DSTATE) // 96
#define SPLITK_XPROJ 8

// tcgen05 is only legal on arch-specific ("a") targets. The harness also
// compiles a plain compute_103/sm_103 pass; give that pass an mma.sync path.
#if defined(__CUDA_ARCH_FEAT_SM103_ALL) || defined(__CUDA_ARCH_FEAT_SM100_ALL) || defined(__CUDA_ARCH_FEAT_SM101_ALL)
#define HAS_TCGEN05 1
#else
#define HAS_TCGEN05 0
#endif

// ---------------------------------------------------------------------------
// Scratch (static device memory; no allocations allowed)
// ---------------------------------------------------------------------------
__device__ float    g_xz[MROWS * NXZ];                       // (xs | z)
__device__ float    g_xsc[MROWS * DINNER];                   // conv+silu output
__device__ float    g_dbc_part[SPLITK_XPROJ * MROWS * NDBC];
__device__ float    g_dbc[MROWS * NDBC];
__device__ float    g_delta[MROWS * DINNER];
__device__ unsigned g_xt[MROWS * DMODEL];                    // x in tf32
__device__ unsigned g_wt_in[NXZ * DMODEL];                   // in_proj_w tf32
__device__ unsigned g_wt_out[DMODEL * DINNER];               // out_proj_w tf32
__device__ unsigned g_yt[MROWS * DINNER];                    // scan output tf32

// ---------------------------------------------------------------------------
// Small PTX helpers
// ---------------------------------------------------------------------------
__device__ __forceinline__ unsigned f2tf32(float x) {
    unsigned r;
    asm("cvt.rna.tf32.f32 %0, %1;" : "=r"(r) : "f"(x));
    return r;
}

__device__ __forceinline__ uint32_t smem_u32(const void* p) {
    uint32_t a;
    asm("{ .reg .u64 t; cvta.to.shared.u64 t, %1; cvt.u32.u64 %0, t; }"
        : "=r"(a) : "l"(p));
    return a;
}

__device__ __forceinline__ void cp_async16(uint32_t smem_addr, const void* gptr) {
    asm volatile("cp.async.cg.shared.global [%0], [%1], 16;"
                 :: "r"(smem_addr), "l"(gptr) : "memory");
}
__device__ __forceinline__ void cp_async_commit() {
    asm volatile("cp.async.commit_group;" ::: "memory");
}
__device__ __forceinline__ void cp_async_wait_all() {
    asm volatile("cp.async.wait_group 0;" ::: "memory");
}

#if HAS_TCGEN05
__device__ __forceinline__ uint32_t elect_one() {
    uint32_t pred;
    asm volatile("{\n .reg .pred p;\n elect.sync _|p, 0xFFFFFFFF;\n"
                 " selp.b32 %0, 1, 0, p;\n}" : "=r"(pred));
    return pred;
}

__device__ __forceinline__ void mbar_init(uint32_t addr, uint32_t cnt) {
    asm volatile("mbarrier.init.shared.b64 [%0], %1;" :: "r"(addr), "r"(cnt) : "memory");
}
__device__ __forceinline__ void mbar_inval(uint32_t addr) {
    asm volatile("mbarrier.inval.shared.b64 [%0];" :: "r"(addr) : "memory");
}
__device__ __forceinline__ void mbar_wait_parity(uint32_t addr, uint32_t parity) {
    asm volatile(
        "{\n .reg .pred P;\n"
        "WAIT_%=:\n"
        " mbarrier.try_wait.parity.acquire.cta.shared::cta.b64 P, [%0], %1, 0x989680;\n"
        " @P bra.uni DONE_%=;\n"
        " bra.uni WAIT_%=;\n"
        "DONE_%=:\n}"
        :: "r"(addr), "r"(parity) : "memory");
}

// 64-bit SMEM matrix descriptor: SW128, Blackwell, LBO=1, SBO=64
__device__ __forceinline__ uint64_t smem_desc_sw128(uint32_t addr) {
    const uint64_t base =
        (uint64_t(2) << 61) | (uint64_t(1) << 46) |
        (uint64_t(64) << 32) | (uint64_t(1) << 16);
    return base | ((uint64_t)(addr >> 4) & 0x3FFF);
}

__device__ __forceinline__ void mma_tf32_ss(uint32_t d_tmem, uint64_t a_desc,
                                            uint64_t b_desc, uint32_t idesc,
                                            uint32_t enable) {
    asm volatile(
        "{\n .reg .pred p;\n"
        " setp.ne.u32 p, %5, 0;\n"
        " tcgen05.mma.cta_group::1.kind::tf32 [%0], %1, %2, %3, {%4, %4, %4, %4}, p;\n"
        "}"
        :: "r"(d_tmem), "l"(a_desc), "l"(b_desc), "r"(idesc), "r"(0u), "r"(enable)
        : "memory");
}
#else
__device__ __forceinline__ void mma_m16n8k8_tf32(float c[4], const unsigned a[4],
                                                 const unsigned b[2]) {
    asm volatile(
        "mma.sync.aligned.m16n8k8.row.col.f32.tf32.tf32.f32 "
        "{%0,%1,%2,%3}, {%4,%5,%6,%7}, {%8,%9}, {%0,%1,%2,%3};\n"
        : "+f"(c[0]), "+f"(c[1]), "+f"(c[2]), "+f"(c[3])
        : "r"(a[0]), "r"(a[1]), "r"(a[2]), "r"(a[3]), "r"(b[0]), "r"(b[1]));
}
#endif

// ---------------------------------------------------------------------------
// Elementwise fp32 -> tf32(rna) conversion (vectorized)
// ---------------------------------------------------------------------------
__global__ void cvt_tf32_kernel(const float4* __restrict__ in,
                                uint4* __restrict__ out, int n4)
{
    const int i = blockIdx.x * blockDim.x + threadIdx.x;
    if (i >= n4) return;
    float4 v = in[i];
    out[i] = make_uint4(f2tf32(v.x), f2tf32(v.y), f2tf32(v.z), f2tf32(v.w));
}

// ---------------------------------------------------------------------------
// TF32 tensor GEMM on PRE-CONVERTED tf32 inputs (same as R9 passing version)
// ---------------------------------------------------------------------------
__global__ void __launch_bounds__(128, 4) tgemm_tc(
    const unsigned* __restrict__ A, const unsigned* __restrict__ B,
    float* __restrict__ C, int K, int lda, int ldb, int ldc)
{
    __shared__ __align__(1024) unsigned As[128 * 32];   // 16 KB
    __shared__ __align__(1024) unsigned Bs[128 * 32];   // 16 KB
#if HAS_TCGEN05
    __shared__ __align__(8) unsigned long long mbar_s;
    __shared__ unsigned tptr_s;
#endif

    const int tid = threadIdx.x;
    const int wid = tid >> 5, lane = tid & 31;
    const int bm = blockIdx.y * 128;
    const int bn = blockIdx.x * 128;

    const int r0 = tid >> 3;      // 0..15
    const int c4 = tid & 7;       // 0..7

    const unsigned* Ap = A + (size_t)(bm + r0) * lda + c4 * 4;
    const unsigned* Bp = B + (size_t)(bn + r0) * ldb + c4 * 4;
    const int nch = K / 32;

    const uint32_t s_as = smem_u32(As);
    const uint32_t s_bs = smem_u32(Bs);

#if HAS_TCGEN05
    const uint32_t s_mbar = smem_u32(&mbar_s);
    const uint32_t s_tptr = smem_u32(&tptr_s);

    if (wid == 0) {
        asm volatile("tcgen05.alloc.cta_group::1.sync.aligned.shared::cta.b32 [%0], %1;"
                     :: "r"(s_tptr), "r"(128u) : "memory");
        asm volatile("tcgen05.relinquish_alloc_permit.cta_group::1.sync.aligned;");
    }
    if (tid == 0) mbar_init(s_mbar, 1);
    __syncthreads();

    uint32_t tmem;
    asm volatile("ld.shared.b32 %0, [%1];" : "=r"(tmem) : "r"(s_tptr));

    const uint32_t idesc = (1u << 4) | (2u << 7) | (2u << 10) |
                           ((128u / 8) << 17) | ((128u / 16) << 24);

    const uint64_t adesc0 = smem_desc_sw128(s_as);
    const uint64_t bdesc0 = smem_desc_sw128(s_bs);
    const bool leader = (wid == 0) && elect_one();

    for (int c = 0; c < nch; c++) {
        if (c > 0) mbar_wait_parity(s_mbar, (c - 1) & 1);

#pragma unroll
        for (int i = 0; i < 8; i++) {
            const int row = r0 + i * 16;
            unsigned off = row * 128 + c4 * 16;
            unsigned sw = off ^ ((off >> 3) & 0x70);
            cp_async16(s_as + sw, Ap + (size_t)(i * 16) * lda + c * 32);
            cp_async16(s_bs + sw, Bp + (size_t)(i * 16) * ldb + c * 32);
        }
        cp_async_commit();
        cp_async_wait_all();
        asm volatile("fence.proxy.async.shared::cta;" ::: "memory");
        __syncthreads();

        if (leader) {
#pragma unroll
            for (int ks = 0; ks < 4; ks++) {
                mma_tf32_ss(tmem, adesc0 + ks * 2, bdesc0 + ks * 2, idesc,
                            (c > 0 || ks > 0) ? 1u : 0u);
            }
            asm volatile(
                "tcgen05.commit.cta_group::1.mbarrier::arrive::one.shared::cluster.b64 [%0];"
                :: "r"(s_mbar) : "memory");
        }
    }

    mbar_wait_parity(s_mbar, (nch - 1) & 1);
    asm volatile("tcgen05.fence::after_thread_sync;" ::: "memory");

    const int row = bm + wid * 32 + lane;
    float* Crow = C + (size_t)row * ldc + bn;
#pragma unroll
    for (int g = 0; g < 4; g++) {
        uint32_t d[32];
        asm volatile(
            "tcgen05.ld.sync.aligned.32x32b.x32.b32 "
            "{%0,%1,%2,%3,%4,%5,%6,%7,%8,%9,%10,%11,%12,%13,%14,%15,"
            "%16,%17,%18,%19,%20,%21,%22,%23,%24,%25,%26,%27,%28,%29,%30,%31}, [%32];"
            : "=r"(d[0]), "=r"(d[1]), "=r"(d[2]), "=r"(d[3]),
              "=r"(d[4]), "=r"(d[5]), "=r"(d[6]), "=r"(d[7]),
              "=r"(d[8]), "=r"(d[9]), "=r"(d[10]), "=r"(d[11]),
              "=r"(d[12]), "=r"(d[13]), "=r"(d[14]), "=r"(d[15]),
              "=r"(d[16]), "=r"(d[17]), "=r"(d[18]), "=r"(d[19]),
              "=r"(d[20]), "=r"(d[21]), "=r"(d[22]), "=r"(d[23]),
              "=r"(d[24]), "=r"(d[25]), "=r"(d[26]), "=r"(d[27]),
              "=r"(d[28]), "=r"(d[29]), "=r"(d[30]), "=r"(d[31])
            : "r"(tmem + g * 32));
        asm volatile("tcgen05.wait::ld.sync.aligned;" ::: "memory");
#pragma unroll
        for (int v = 0; v < 8; v++) {
            *(float4*)(Crow + g * 32 + v * 4) = make_float4(
                __uint_as_float(d[v * 4 + 0]), __uint_as_float(d[v * 4 + 1]),
                __uint_as_float(d[v * 4 + 2]), __uint_as_float(d[v * 4 + 3]));
        }
    }

    __syncthreads();
    if (tid == 0) mbar_inval(s_mbar);
    __syncthreads();
    if (wid == 0) {
        asm volatile("tcgen05.dealloc.cta_group::1.sync.aligned.b32 %0, %1;"
                     :: "r"(tmem), "r"(128u));
    }
#else
    const int wm = wid * 32;
    const int q = lane & 3;
    const int r = lane >> 2;

    float acc[2][16][4];
#pragma unroll
    for (int i = 0; i < 2; i++)
#pragma unroll
        for (int j = 0; j < 16; j++)
#pragma unroll
            for (int t = 0; t < 4; t++) acc[i][j][t] = 0.f;

    for (int c = 0; c < nch; c++) {
        __syncthreads();
#pragma unroll
        for (int i = 0; i < 8; i++) {
            const int row = r0 + i * 16;
            uint4 av = *(const uint4*)(Ap + (size_t)(i * 16) * lda + c * 32);
            uint4 bv = *(const uint4*)(Bp + (size_t)(i * 16) * ldb + c * 32);
            *(uint4*)&As[row * 32 + c4 * 4] = av;
            *(uint4*)&Bs[row * 32 + c4 * 4] = bv;
        }
        __syncthreads();

#pragma unroll
        for (int kk = 0; kk < 32; kk += 8) {
            unsigned af[2][4];
#pragma unroll
            for (int i = 0; i < 2; i++) {
                const int mrow = wm + i * 16;
                af[i][0] = As[(mrow + r) * 32 + kk + q];
                af[i][1] = As[(mrow + r + 8) * 32 + kk + q];
                af[i][2] = As[(mrow + r) * 32 + kk + q + 4];
                af[i][3] = As[(mrow + r + 8) * 32 + kk + q + 4];
            }
#pragma unroll
            for (int j = 0; j < 16; j++) {
                unsigned bf[2];
                bf[0] = Bs[(j * 8 + r) * 32 + kk + q];
                bf[1] = Bs[(j * 8 + r) * 32 + kk + q + 4];
#pragma unroll
                for (int i = 0; i < 2; i++)
                    mma_m16n8k8_tf32(acc[i][j], af[i], bf);
            }
        }
    }

#pragma unroll
    for (int i = 0; i < 2; i++) {
        const int row = bm + wm + i * 16 + r;
#pragma unroll
        for (int j = 0; j < 16; j++) {
            const int col = bn + j * 8 + q * 2;
            *(float2*)&C[(size_t)row * ldc + col] =
                make_float2(acc[i][j][0], acc[i][j][1]);
            *(float2*)&C[(size_t)(row + 8) * ldc + col] =
                make_float2(acc[i][j][2], acc[i][j][3]);
        }
    }
#endif
}

// ---------------------------------------------------------------------------
// FP32 SGEMM for the small dt-path GEMMs (precision of delta before exp).
// ---------------------------------------------------------------------------
template<int EPI>
__global__ void __launch_bounds__(256, 2) sgemm128(
    const float* __restrict__ A, const float* __restrict__ B,
    float* __restrict__ C, int M, int N, int K,
    int lda, int ldb, int ldc, int kChunk,
    const float* __restrict__ bias)
{
    __shared__ float As[8][128];
    __shared__ float Bs[8][128];

    const int tid = threadIdx.x;
    const int bm = blockIdx.y * 128;
    const int bn = blockIdx.x * 128;
    int kBegin = blockIdx.z * kChunk;
    int kEnd   = kBegin + kChunk; if (kEnd > K) kEnd = K;
    C += (size_t)blockIdx.z * (size_t)M * (size_t)ldc;

    const int ar = tid >> 1;
    const int ac = (tid & 1) * 4;
    const int ty = tid >> 4;
    const int tx = tid & 15;

    float acc[8][8];
#pragma unroll
    for (int i = 0; i < 8; i++)
#pragma unroll
        for (int j = 0; j < 8; j++) acc[i][j] = 0.f;

    const float* Aptr = A + (size_t)(bm + ar) * lda + ac;
    const int brow = bn + ar;
    const float* Bptr = B + (size_t)brow * ldb + ac;
    const bool bvalid = (brow < N);

    for (int k0 = kBegin; k0 < kEnd; k0 += 8) {
        float4 av = *(const float4*)(Aptr + k0);
        float4 bv = make_float4(0.f, 0.f, 0.f, 0.f);
        if (bvalid) bv = *(const float4*)(Bptr + k0);

        __syncthreads();
        As[ac + 0][ar] = av.x; As[ac + 1][ar] = av.y;
        As[ac + 2][ar] = av.z; As[ac + 3][ar] = av.w;
        Bs[ac + 0][ar] = bv.x; Bs[ac + 1][ar] = bv.y;
        Bs[ac + 2][ar] = bv.z; Bs[ac + 3][ar] = bv.w;
        __syncthreads();

#pragma unroll
        for (int kk = 0; kk < 8; kk++) {
            float a[8], b[8];
#pragma unroll
            for (int i = 0; i < 8; i++) a[i] = As[kk][ty * 8 + i];
#pragma unroll
            for (int j = 0; j < 8; j++) b[j] = Bs[kk][tx * 8 + j];
#pragma unroll
            for (int i = 0; i < 8; i++)
#pragma unroll
                for (int j = 0; j < 8; j++)
                    acc[i][j] = fmaf(a[i], b[j], acc[i][j]);
        }
    }

#pragma unroll
    for (int i = 0; i < 8; i++) {
        const int row = bm + ty * 8 + i;
#pragma unroll
        for (int j = 0; j < 8; j++) {
            const int col = bn + tx * 8 + j;
            if (col < N) {
                float v = acc[i][j];
                if (EPI == 1) {
                    v += bias[col];
                    v = fmaxf(v, 0.f) + log1pf(__expf(-fabsf(v)));
                }
                C[(size_t)row * ldc + col] = v;
            }
        }
    }
}

// ---------------------------------------------------------------------------
// Depthwise causal conv (k=4) + bias + SiLU
// ---------------------------------------------------------------------------
__global__ void conv_silu_kernel(const float* __restrict__ xz,
                                 const float* __restrict__ cw,
                                 const float* __restrict__ cb,
                                 float* __restrict__ xsc)
{
    const int idx = blockIdx.x * blockDim.x + threadIdx.x;
    if (idx >= MROWS * DINNER) return;
    const int d = idx & (DINNER - 1);
    const int m = idx >> 11;
    const int l = m & (LSEQ - 1);

    const float w0 = cw[d * 4 + 0], w1 = cw[d * 4 + 1];
    const float w2 = cw[d * 4 + 2], w3 = cw[d * 4 + 3];
    const float* p = xz + (size_t)m * NXZ + d;

    float acc = cb[d] + w3 * p[0];
    if (l >= 1) acc = fmaf(w2, p[-NXZ],     acc);
    if (l >= 2) acc = fmaf(w1, p[-2 * NXZ], acc);
    if (l >= 3) acc = fmaf(w0, p[-3 * NXZ], acc);

    xsc[idx] = acc / (1.f + __expf(-acc));
}

// ---------------------------------------------------------------------------
// Split-K reduction for x_proj
// ---------------------------------------------------------------------------
__global__ void reduce_dbc_kernel(const float* __restrict__ part,
                                  float* __restrict__ out)
{
    const int idx = blockIdx.x * blockDim.x + threadIdx.x;
    if (idx >= MROWS * NDBC) return;
    float s = 0.f;
#pragma unroll
    for (int j = 0; j < SPLITK_XPROJ; j++)
        s += part[(size_t)j * MROWS * NDBC + idx];
    out[idx] = s;
}

// ---------------------------------------------------------------------------
// Selective scan v2: CTA = 16 channels x 16 states; sequence in chunks of 16
// staged through smem (coalesced loads, register prefetch of next chunk).
// Same math/order as v1 per channel. Writes tf32 gated output, coalesced.
// ---------------------------------------------------------------------------
#define SCH   16   // channels per CTA
#define SCHK  16   // l-steps per chunk

__global__ void __launch_bounds__(256) scan_kernel(
    const float* __restrict__ delta,
    const float* __restrict__ xsc,
    const float* __restrict__ dbc,
    const float* __restrict__ xz,
    const float* __restrict__ A_log,
    const float* __restrict__ Dp,
    unsigned* __restrict__ yt)
{
    __shared__ float sD[SCHK][SCH];
    __shared__ float sX[SCHK][SCH];
    __shared__ float sZ[SCHK][SCH];
    __shared__ float sB[SCHK][DSTATE];
    __shared__ float sC[SCHK][DSTATE];
    __shared__ unsigned sY[SCHK][SCH];

    const int tid = threadIdx.x;
    const int ch  = tid >> 4;          // channel-local 0..15
    const int n   = tid & 15;          // state 0..15
    const int b   = blockIdx.x >> 7;   // 128 blocks per batch
    const int d0  = (blockIdx.x & 127) * SCH;

    // loader role: element (lrow, lcol) of each 16x16 tile
    const int lrow = tid >> 4;
    const int lcol = tid & 15;

    const float An = -__expf(A_log[(d0 + ch) * DSTATE + n]);
    const float Dd = Dp[d0 + ch];

    const size_t rowD = (size_t)DINNER;

    float rD, rX, rZ, rB, rC;
    auto issue_loads = [&](int j) {
        const size_t m = (size_t)b * LSEQ + j * SCHK + lrow;
        rD = delta[m * rowD + d0 + lcol];
        rX = xsc  [m * rowD + d0 + lcol];
        rZ = xz   [m * NXZ + DINNER + d0 + lcol];
        rB = dbc  [m * NDBC + DTRANK + lcol];
        rC = dbc  [m * NDBC + DTRANK + DSTATE + lcol];
    };

    // prologue: chunk 0 into smem
    issue_loads(0);
    sD[lrow][lcol] = rD; sX[lrow][lcol] = rX; sZ[lrow][lcol] = rZ;
    sB[lrow][lcol] = rB; sC[lrow][lcol] = rC;
    __syncthreads();

    float h = 0.f;
    const int nchk = LSEQ / SCHK;   // 64
    for (int j = 0; j < nchk; j++) {
        if (j + 1 < nchk) issue_loads(j + 1);   // LDGs overlap compute below

#pragma unroll
        for (int s = 0; s < SCHK; s++) {
            const float dl = sD[s][ch];
            const float xv = sX[s][ch];
            const float Bv = sB[s][n];
            const float Cv = sC[s][n];

            const float dA = __expf(dl * An);
            h = fmaf(dA, h, dl * xv * Bv);

            float part = h * Cv;
            part += __shfl_xor_sync(0xffffffffu, part, 8, 16);
            part += __shfl_xor_sync(0xffffffffu, part, 4, 16);
            part += __shfl_xor_sync(0xffffffffu, part, 2, 16);
            part += __shfl_xor_sync(0xffffffffu, part, 1, 16);

            if (n == 0) {
                const float yv = part + Dd * xv;
                const float zv = sZ[s][ch];
                const float sz = zv / (1.f + __expf(-zv));
                sY[s][ch] = f2tf32(yv * sz);
            }
        }
        __syncthreads();   // sY complete; smem tiles free for reuse

        // coalesced output of chunk j
        {
            const size_t m = (size_t)b * LSEQ + j * SCHK + lrow;
            yt[m * rowD + d0 + lcol] = sY[lrow][lcol];
        }

        if (j + 1 < nchk) {
            sD[lrow][lcol] = rD; sX[lrow][lcol] = rX; sZ[lrow][lcol] = rZ;
            sB[lrow][lcol] = rB; sC[lrow][lcol] = rC;
        }
        __syncthreads();
    }
}

// ---------------------------------------------------------------------------
// Launch
// ---------------------------------------------------------------------------
extern "C" void kernel_launch(void* const* d_in, const int* in_sizes, int n_in,
                              void* d_out, int out_size)
{
    const float* x         = (const float*)d_in[0];
    const float* in_proj_w = (const float*)d_in[1];
    const float* conv_w    = (const float*)d_in[2];
    const float* conv_b    = (const float*)d_in[3];
    const float* x_proj_w  = (const float*)d_in[4];
    const float* dt_proj_w = (const float*)d_in[5];
    const float* dt_proj_b = (const float*)d_in[6];
    const float* A_log     = (const float*)d_in[7];
    const float* Dvec      = (const float*)d_in[8];
    const float* out_proj_w= (const float*)d_in[9];
    float* out = (float*)d_out;

    float *xz, *xsc, *dbc_part, *dbc, *delta;
    unsigned *xt, *wt_in, *wt_out, *yt;
    cudaGetSymbolAddress((void**)&xz,       g_xz);
    cudaGetSymbolAddress((void**)&xsc,      g_xsc);
    cudaGetSymbolAddress((void**)&dbc_part, g_dbc_part);
    cudaGetSymbolAddress((void**)&dbc,      g_dbc);
    cudaGetSymbolAddress((void**)&delta,    g_delta);
    cudaGetSymbolAddress((void**)&xt,       g_xt);
    cudaGetSymbolAddress((void**)&wt_in,    g_wt_in);
    cudaGetSymbolAddress((void**)&wt_out,   g_wt_out);
    cudaGetSymbolAddress((void**)&yt,       g_yt);

    // 0) pre-convert fp32 -> tf32 (once per call)
    {
        int n4;
        n4 = (MROWS * DMODEL) / 4;
        cvt_tf32_kernel<<<(n4 + 255) / 256, 256>>>((const float4*)x, (uint4*)xt, n4);
        n4 = (NXZ * DMODEL) / 4;
        cvt_tf32_kernel<<<(n4 + 255) / 256, 256>>>((const float4*)in_proj_w, (uint4*)wt_in, n4);
        n4 = (DMODEL * DINNER) / 4;
        cvt_tf32_kernel<<<(n4 + 255) / 256, 256>>>((const float4*)out_proj_w, (uint4*)wt_out, n4);
    }

    // 1) xz = x @ in_proj_w^T  (2048 x 4096, K=1024)  — tcgen05 TF32
    {
        dim3 grid(NXZ / 128, MROWS / 128);
        tgemm_tc<<<grid, 128>>>(xt, wt_in, xz, DMODEL, DMODEL, DMODEL, NXZ);
    }

    // 2) depthwise conv + bias + silu -> xsc
    {
        int n = MROWS * DINNER;
        conv_silu_kernel<<<(n + 255) / 256, 256>>>(xz, conv_w, conv_b, xsc);
    }

    // 3) dbc = xsc @ x_proj_w^T  (2048 x 96, K=2048), fp32, split-K=8
    {
        dim3 grid(1, MROWS / 128, SPLITK_XPROJ);
        sgemm128<0><<<grid, 256>>>(xsc, x_proj_w, dbc_part,
                                   MROWS, NDBC, DINNER,
                                   DINNER, DINNER, NDBC, DINNER / SPLITK_XPROJ,
                                   nullptr);
        int n = MROWS * NDBC;
        reduce_dbc_kernel<<<(n + 255) / 256, 256>>>(dbc_part, dbc);
    }

    // 4) delta = softplus(dbc[:, :64] @ dt_proj_w^T + dt_proj_b)  fp32
    {
        dim3 grid(DINNER / 128, MROWS / 128, 1);
        sgemm128<1><<<grid, 256>>>(dbc, dt_proj_w, delta,
                                   MROWS, DINNER, DTRANK,
                                   NDBC, DTRANK, DINNER, DTRANK, dt_proj_b);
    }

    // 5) selective scan v2 -> yt (tf32)
    {
        int blocks = (BSZ * DINNER) / SCH;   // 256
        scan_kernel<<<blocks, 256>>>(delta, xsc, dbc, xz, A_log, Dvec, yt);
    }

    // 6) out = y @ out_proj_w^T  (2048 x 1024, K=2048) — tcgen05 TF32
    {
        dim3 grid(DMODEL / 128, MROWS / 128);
        tgemm_tc<<<grid, 128>>>(yt, wt_out, out, DINNER, DINNER, DINNER, DMODEL);
    }
}

// round 11
// speedup vs baseline: 2.7256x; 1.0853x over previous
#include <cuda_runtime.h>
#include <cuda_bf16.h>
#include <math.h>
#include <stdint.h>

// ---------------------------------------------------------------------------
// Problem constants
// ---------------------------------------------------------------------------
#define BSZ     2
#define LSEQ    1024
#define DMODEL  1024
#define DINNER  2048
#define DSTATE  16
#define DTRANK  64
#define MROWS   (BSZ * LSEQ)        // 2048
#define NXZ     (2 * DINNER)        // 4096
#define NDBC    (DTRANK + 2*DSTATE) // 96
#define SPLITK_XPROJ 16
#define SPLITK_OPROJ 2

// tcgen05 is only legal on arch-specific ("a") targets. The harness also
// compiles a plain compute_103/sm_103 pass; give that pass an mma.sync path.
#if defined(__CUDA_ARCH_FEAT_SM103_ALL) || defined(__CUDA_ARCH_FEAT_SM100_ALL) || defined(__CUDA_ARCH_FEAT_SM101_ALL)
#define HAS_TCGEN05 1
#else
#define HAS_TCGEN05 0
#endif

// ---------------------------------------------------------------------------
// Scratch (static device memory; no allocations allowed)
// ---------------------------------------------------------------------------
__device__ float    g_xz[MROWS * NXZ];                       // (xs | z)
__device__ float    g_xsc[MROWS * DINNER];                   // conv+silu output
__device__ float    g_dbc_part[SPLITK_XPROJ * MROWS * NDBC];
__device__ float    g_dbc[MROWS * NDBC];
__device__ float    g_delta[MROWS * DINNER];
__device__ unsigned g_xt[MROWS * DMODEL];                    // x in tf32
__device__ unsigned g_wt_in[NXZ * DMODEL];                   // in_proj_w tf32
__device__ unsigned g_wt_out[DMODEL * DINNER];               // out_proj_w tf32
__device__ unsigned g_yt[MROWS * DINNER];                    // scan output tf32
__device__ float    g_opart[SPLITK_OPROJ * MROWS * DMODEL];  // out_proj partials

// ---------------------------------------------------------------------------
// Small PTX helpers
// ---------------------------------------------------------------------------
__device__ __forceinline__ unsigned f2tf32(float x) {
    unsigned r;
    asm("cvt.rna.tf32.f32 %0, %1;" : "=r"(r) : "f"(x));
    return r;
}

__device__ __forceinline__ uint32_t smem_u32(const void* p) {
    uint32_t a;
    asm("{ .reg .u64 t; cvta.to.shared.u64 t, %1; cvt.u32.u64 %0, t; }"
        : "=r"(a) : "l"(p));
    return a;
}

__device__ __forceinline__ void cp_async16(uint32_t smem_addr, const void* gptr) {
    asm volatile("cp.async.cg.shared.global [%0], [%1], 16;"
                 :: "r"(smem_addr), "l"(gptr) : "memory");
}
__device__ __forceinline__ void cp_async_commit() {
    asm volatile("cp.async.commit_group;" ::: "memory");
}
__device__ __forceinline__ void cp_async_wait_all() {
    asm volatile("cp.async.wait_group 0;" ::: "memory");
}

#if HAS_TCGEN05
__device__ __forceinline__ uint32_t elect_one() {
    uint32_t pred;
    asm volatile("{\n .reg .pred p;\n elect.sync _|p, 0xFFFFFFFF;\n"
                 " selp.b32 %0, 1, 0, p;\n}" : "=r"(pred));
    return pred;
}

__device__ __forceinline__ void mbar_init(uint32_t addr, uint32_t cnt) {
    asm volatile("mbarrier.init.shared.b64 [%0], %1;" :: "r"(addr), "r"(cnt) : "memory");
}
__device__ __forceinline__ void mbar_inval(uint32_t addr) {
    asm volatile("mbarrier.inval.shared.b64 [%0];" :: "r"(addr) : "memory");
}
__device__ __forceinline__ void mbar_wait_parity(uint32_t addr, uint32_t parity) {
    asm volatile(
        "{\n .reg .pred P;\n"
        "WAIT_%=:\n"
        " mbarrier.try_wait.parity.acquire.cta.shared::cta.b64 P, [%0], %1, 0x989680;\n"
        " @P bra.uni DONE_%=;\n"
        " bra.uni WAIT_%=;\n"
        "DONE_%=:\n}"
        :: "r"(addr), "r"(parity) : "memory");
}

// 64-bit SMEM matrix descriptor: SW128, Blackwell, LBO=1, SBO=64
__device__ __forceinline__ uint64_t smem_desc_sw128(uint32_t addr) {
    const uint64_t base =
        (uint64_t(2) << 61) | (uint64_t(1) << 46) |
        (uint64_t(64) << 32) | (uint64_t(1) << 16);
    return base | ((uint64_t)(addr >> 4) & 0x3FFF);
}

__device__ __forceinline__ void mma_tf32_ss(uint32_t d_tmem, uint64_t a_desc,
                                            uint64_t b_desc, uint32_t idesc,
                                            uint32_t enable) {
    asm volatile(
        "{\n .reg .pred p;\n"
        " setp.ne.u32 p, %5, 0;\n"
        " tcgen05.mma.cta_group::1.kind::tf32 [%0], %1, %2, %3, {%4, %4, %4, %4}, p;\n"
        "}"
        :: "r"(d_tmem), "l"(a_desc), "l"(b_desc), "r"(idesc), "r"(0u), "r"(enable)
        : "memory");
}
#else
__device__ __forceinline__ void mma_m16n8k8_tf32(float c[4], const unsigned a[4],
                                                 const unsigned b[2]) {
    asm volatile(
        "mma.sync.aligned.m16n8k8.row.col.f32.tf32.tf32.f32 "
        "{%0,%1,%2,%3}, {%4,%5,%6,%7}, {%8,%9}, {%0,%1,%2,%3};\n"
        : "+f"(c[0]), "+f"(c[1]), "+f"(c[2]), "+f"(c[3])
        : "r"(a[0]), "r"(a[1]), "r"(a[2]), "r"(a[3]), "r"(b[0]), "r"(b[1]));
}
#endif

// ---------------------------------------------------------------------------
// Fused fp32 -> tf32(rna) conversion of the three GEMM operands (one launch)
// ---------------------------------------------------------------------------
__global__ void cvt3_tf32_kernel(const float4* __restrict__ a, uint4* __restrict__ oa, int na4,
                                 const float4* __restrict__ b, uint4* __restrict__ ob, int nb4,
                                 const float4* __restrict__ c, uint4* __restrict__ oc, int nc4)
{
    int i = blockIdx.x * blockDim.x + threadIdx.x;
    if (i < na4) {
        float4 v = a[i];
        oa[i] = make_uint4(f2tf32(v.x), f2tf32(v.y), f2tf32(v.z), f2tf32(v.w));
        return;
    }
    i -= na4;
    if (i < nb4) {
        float4 v = b[i];
        ob[i] = make_uint4(f2tf32(v.x), f2tf32(v.y), f2tf32(v.z), f2tf32(v.w));
        return;
    }
    i -= nb4;
    if (i < nc4) {
        float4 v = c[i];
        oc[i] = make_uint4(f2tf32(v.x), f2tf32(v.y), f2tf32(v.z), f2tf32(v.w));
    }
}

// ---------------------------------------------------------------------------
// TF32 tensor GEMM on PRE-CONVERTED tf32 inputs, with optional split-K:
// blockIdx.z takes K-chunk [z*kChunk, (z+1)*kChunk) and writes to
// C + z*splitStride. C[m,n] = sum_k A[m,k]*B[n,k].
// Requires M%128==0, N%128==0, kChunk%32==0, lda/ldb%4==0.
// ---------------------------------------------------------------------------
__global__ void __launch_bounds__(128, 4) tgemm_tc(
    const unsigned* __restrict__ A, const unsigned* __restrict__ B,
    float* __restrict__ C, int lda, int ldb, int ldc,
    int kChunk, size_t splitStride)
{
    __shared__ __align__(1024) unsigned As[128 * 32];   // 16 KB
    __shared__ __align__(1024) unsigned Bs[128 * 32];   // 16 KB
#if HAS_TCGEN05
    __shared__ __align__(8) unsigned long long mbar_s;
    __shared__ unsigned tptr_s;
#endif

    const int tid = threadIdx.x;
    const int wid = tid >> 5, lane = tid & 31;
    const int bm = blockIdx.y * 128;
    const int bn = blockIdx.x * 128;
    const int kBegin = blockIdx.z * kChunk;
    C += (size_t)blockIdx.z * splitStride;

    const int r0 = tid >> 3;      // 0..15
    const int c4 = tid & 7;       // 0..7

    const unsigned* Ap = A + (size_t)(bm + r0) * lda + c4 * 4 + kBegin;
    const unsigned* Bp = B + (size_t)(bn + r0) * ldb + c4 * 4 + kBegin;
    const int nch = kChunk / 32;

    const uint32_t s_as = smem_u32(As);
    const uint32_t s_bs = smem_u32(Bs);

#if HAS_TCGEN05
    const uint32_t s_mbar = smem_u32(&mbar_s);
    const uint32_t s_tptr = smem_u32(&tptr_s);

    if (wid == 0) {
        asm volatile("tcgen05.alloc.cta_group::1.sync.aligned.shared::cta.b32 [%0], %1;"
                     :: "r"(s_tptr), "r"(128u) : "memory");
        asm volatile("tcgen05.relinquish_alloc_permit.cta_group::1.sync.aligned;");
    }
    if (tid == 0) mbar_init(s_mbar, 1);
    __syncthreads();

    uint32_t tmem;
    asm volatile("ld.shared.b32 %0, [%1];" : "=r"(tmem) : "r"(s_tptr));

    const uint32_t idesc = (1u << 4) | (2u << 7) | (2u << 10) |
                           ((128u / 8) << 17) | ((128u / 16) << 24);

    const uint64_t adesc0 = smem_desc_sw128(s_as);
    const uint64_t bdesc0 = smem_desc_sw128(s_bs);
    const bool leader = (wid == 0) && elect_one();

    for (int c = 0; c < nch; c++) {
        if (c > 0) mbar_wait_parity(s_mbar, (c - 1) & 1);

#pragma unroll
        for (int i = 0; i < 8; i++) {
            const int row = r0 + i * 16;
            unsigned off = row * 128 + c4 * 16;
            unsigned sw = off ^ ((off >> 3) & 0x70);
            cp_async16(s_as + sw, Ap + (size_t)(i * 16) * lda + c * 32);
            cp_async16(s_bs + sw, Bp + (size_t)(i * 16) * ldb + c * 32);
        }
        cp_async_commit();
        cp_async_wait_all();
        asm volatile("fence.proxy.async.shared::cta;" ::: "memory");
        __syncthreads();

        if (leader) {
#pragma unroll
            for (int ks = 0; ks < 4; ks++) {
                mma_tf32_ss(tmem, adesc0 + ks * 2, bdesc0 + ks * 2, idesc,
                            (c > 0 || ks > 0) ? 1u : 0u);
            }
            asm volatile(
                "tcgen05.commit.cta_group::1.mbarrier::arrive::one.shared::cluster.b64 [%0];"
                :: "r"(s_mbar) : "memory");
        }
    }

    mbar_wait_parity(s_mbar, (nch - 1) & 1);
    asm volatile("tcgen05.fence::after_thread_sync;" ::: "memory");

    const int row = bm + wid * 32 + lane;
    float* Crow = C + (size_t)row * ldc + bn;
#pragma unroll
    for (int g = 0; g < 4; g++) {
        uint32_t d[32];
        asm volatile(
            "tcgen05.ld.sync.aligned.32x32b.x32.b32 "
            "{%0,%1,%2,%3,%4,%5,%6,%7,%8,%9,%10,%11,%12,%13,%14,%15,"
            "%16,%17,%18,%19,%20,%21,%22,%23,%24,%25,%26,%27,%28,%29,%30,%31}, [%32];"
            : "=r"(d[0]), "=r"(d[1]), "=r"(d[2]), "=r"(d[3]),
              "=r"(d[4]), "=r"(d[5]), "=r"(d[6]), "=r"(d[7]),
              "=r"(d[8]), "=r"(d[9]), "=r"(d[10]), "=r"(d[11]),
              "=r"(d[12]), "=r"(d[13]), "=r"(d[14]), "=r"(d[15]),
              "=r"(d[16]), "=r"(d[17]), "=r"(d[18]), "=r"(d[19]),
              "=r"(d[20]), "=r"(d[21]), "=r"(d[22]), "=r"(d[23]),
              "=r"(d[24]), "=r"(d[25]), "=r"(d[26]), "=r"(d[27]),
              "=r"(d[28]), "=r"(d[29]), "=r"(d[30]), "=r"(d[31])
            : "r"(tmem + g * 32));
        asm volatile("tcgen05.wait::ld.sync.aligned;" ::: "memory");
#pragma unroll
        for (int v = 0; v < 8; v++) {
            *(float4*)(Crow + g * 32 + v * 4) = make_float4(
                __uint_as_float(d[v * 4 + 0]), __uint_as_float(d[v * 4 + 1]),
                __uint_as_float(d[v * 4 + 2]), __uint_as_float(d[v * 4 + 3]));
        }
    }

    __syncthreads();
    if (tid == 0) mbar_inval(s_mbar);
    __syncthreads();
    if (wid == 0) {
        asm volatile("tcgen05.dealloc.cta_group::1.sync.aligned.b32 %0, %1;"
                     :: "r"(tmem), "r"(128u));
    }
#else
    const int wm = wid * 32;
    const int q = lane & 3;
    const int r = lane >> 2;

    float acc[2][16][4];
#pragma unroll
    for (int i = 0; i < 2; i++)
#pragma unroll
        for (int j = 0; j < 16; j++)
#pragma unroll
            for (int t = 0; t < 4; t++) acc[i][j][t] = 0.f;

    for (int c = 0; c < nch; c++) {
        __syncthreads();
#pragma unroll
        for (int i = 0; i < 8; i++) {
            const int row = r0 + i * 16;
            uint4 av = *(const uint4*)(Ap + (size_t)(i * 16) * lda + c * 32);
            uint4 bv = *(const uint4*)(Bp + (size_t)(i * 16) * ldb + c * 32);
            *(uint4*)&As[row * 32 + c4 * 4] = av;
            *(uint4*)&Bs[row * 32 + c4 * 4] = bv;
        }
        __syncthreads();

#pragma unroll
        for (int kk = 0; kk < 32; kk += 8) {
            unsigned af[2][4];
#pragma unroll
            for (int i = 0; i < 2; i++) {
                const int mrow = wm + i * 16;
                af[i][0] = As[(mrow + r) * 32 + kk + q];
                af[i][1] = As[(mrow + r + 8) * 32 + kk + q];
                af[i][2] = As[(mrow + r) * 32 + kk + q + 4];
                af[i][3] = As[(mrow + r + 8) * 32 + kk + q + 4];
            }
#pragma unroll
            for (int j = 0; j < 16; j++) {
                unsigned bf[2];
                bf[0] = Bs[(j * 8 + r) * 32 + kk + q];
                bf[1] = Bs[(j * 8 + r) * 32 + kk + q + 4];
#pragma unroll
                for (int i = 0; i < 2; i++)
                    mma_m16n8k8_tf32(acc[i][j], af[i], bf);
            }
        }
    }

#pragma unroll
    for (int i = 0; i < 2; i++) {
        const int row = bm + wm + i * 16 + r;
#pragma unroll
        for (int j = 0; j < 16; j++) {
            const int col = bn + j * 8 + q * 2;
            *(float2*)&C[(size_t)row * ldc + col] =
                make_float2(acc[i][j][0], acc[i][j][1]);
            *(float2*)&C[(size_t)(row + 8) * ldc + col] =
                make_float2(acc[i][j][2], acc[i][j][3]);
        }
    }
#endif
}

// ---------------------------------------------------------------------------
// FP32 SGEMM for the small dt-path GEMMs (precision of delta before exp).
// ---------------------------------------------------------------------------
template<int EPI>
__global__ void __launch_bounds__(256, 2) sgemm128(
    const float* __restrict__ A, const float* __restrict__ B,
    float* __restrict__ C, int M, int N, int K,
    int lda, int ldb, int ldc, int kChunk,
    const float* __restrict__ bias)
{
    __shared__ float As[8][128];
    __shared__ float Bs[8][128];

    const int tid = threadIdx.x;
    const int bm = blockIdx.y * 128;
    const int bn = blockIdx.x * 128;
    int kBegin = blockIdx.z * kChunk;
    int kEnd   = kBegin + kChunk; if (kEnd > K) kEnd = K;
    C += (size_t)blockIdx.z * (size_t)M * (size_t)ldc;

    const int ar = tid >> 1;
    const int ac = (tid & 1) * 4;
    const int ty = tid >> 4;
    const int tx = tid & 15;

    float acc[8][8];
#pragma unroll
    for (int i = 0; i < 8; i++)
#pragma unroll
        for (int j = 0; j < 8; j++) acc[i][j] = 0.f;

    const float* Aptr = A + (size_t)(bm + ar) * lda + ac;
    const int brow = bn + ar;
    const float* Bptr = B + (size_t)brow * ldb + ac;
    const bool bvalid = (brow < N);

    for (int k0 = kBegin; k0 < kEnd; k0 += 8) {
        float4 av = *(const float4*)(Aptr + k0);
        float4 bv = make_float4(0.f, 0.f, 0.f, 0.f);
        if (bvalid) bv = *(const float4*)(Bptr + k0);

        __syncthreads();
        As[ac + 0][ar] = av.x; As[ac + 1][ar] = av.y;
        As[ac + 2][ar] = av.z; As[ac + 3][ar] = av.w;
        Bs[ac + 0][ar] = bv.x; Bs[ac + 1][ar] = bv.y;
        Bs[ac + 2][ar] = bv.z; Bs[ac + 3][ar] = bv.w;
        __syncthreads();

#pragma unroll
        for (int kk = 0; kk < 8; kk++) {
            float a[8], b[8];
#pragma unroll
            for (int i = 0; i < 8; i++) a[i] = As[kk][ty * 8 + i];
#pragma unroll
            for (int j = 0; j < 8; j++) b[j] = Bs[kk][tx * 8 + j];
#pragma unroll
            for (int i = 0; i < 8; i++)
#pragma unroll
                for (int j = 0; j < 8; j++)
                    acc[i][j] = fmaf(a[i], b[j], acc[i][j]);
        }
    }

#pragma unroll
    for (int i = 0; i < 8; i++) {
        const int row = bm + ty * 8 + i;
#pragma unroll
        for (int j = 0; j < 8; j++) {
            const int col = bn + tx * 8 + j;
            if (col < N) {
                float v = acc[i][j];
                if (EPI == 1) {
                    v += bias[col];
                    v = fmaxf(v, 0.f) + log1pf(__expf(-fabsf(v)));
                }
                C[(size_t)row * ldc + col] = v;
            }
        }
    }
}

// ---------------------------------------------------------------------------
// Depthwise causal conv (k=4) + bias + SiLU
// ---------------------------------------------------------------------------
__global__ void conv_silu_kernel(const float* __restrict__ xz,
                                 const float* __restrict__ cw,
                                 const float* __restrict__ cb,
                                 float* __restrict__ xsc)
{
    const int idx = blockIdx.x * blockDim.x + threadIdx.x;
    if (idx >= MROWS * DINNER) return;
    const int d = idx & (DINNER - 1);
    const int m = idx >> 11;
    const int l = m & (LSEQ - 1);

    const float w0 = cw[d * 4 + 0], w1 = cw[d * 4 + 1];
    const float w2 = cw[d * 4 + 2], w3 = cw[d * 4 + 3];
    const float* p = xz + (size_t)m * NXZ + d;

    float acc = cb[d] + w3 * p[0];
    if (l >= 1) acc = fmaf(w2, p[-NXZ],     acc);
    if (l >= 2) acc = fmaf(w1, p[-2 * NXZ], acc);
    if (l >= 3) acc = fmaf(w0, p[-3 * NXZ], acc);

    xsc[idx] = acc / (1.f + __expf(-acc));
}

// ---------------------------------------------------------------------------
// Split-K reductions
// ---------------------------------------------------------------------------
__global__ void reduce_dbc_kernel(const float* __restrict__ part,
                                  float* __restrict__ out)
{
    const int idx = blockIdx.x * blockDim.x + threadIdx.x;
    if (idx >= MROWS * NDBC) return;
    float s = 0.f;
#pragma unroll
    for (int j = 0; j < SPLITK_XPROJ; j++)
        s += part[(size_t)j * MROWS * NDBC + idx];
    out[idx] = s;
}

__global__ void reduce_out_kernel(const float* __restrict__ part,
                                  float* __restrict__ out)
{
    const int idx = blockIdx.x * blockDim.x + threadIdx.x;
    if (idx >= MROWS * DMODEL) return;
    out[idx] = part[idx] + part[(size_t)MROWS * DMODEL + idx];
}

// ---------------------------------------------------------------------------
// Selective scan v3: CTA = 16 channels x 16 states; chunks of 16 steps staged
// through smem. Per chunk the recurrence is phase-split: (a) precompute
// dA/dBx for all 16 steps, (b) serial h-chain of 16 fmas, (c) 16 independent
// shfl reductions — so the critical path is the fma chain, not exp/shfl.
// Same arithmetic per channel as v2. Writes tf32 gated output, coalesced.
// ---------------------------------------------------------------------------
#define SCH   16   // channels per CTA
#define SCHK  16   // l-steps per chunk

__global__ void __launch_bounds__(256) scan_kernel(
    const float* __restrict__ delta,
    const float* __restrict__ xsc,
    const float* __restrict__ dbc,
    const float* __restrict__ xz,
    const float* __restrict__ A_log,
    const float* __restrict__ Dp,
    unsigned* __restrict__ yt)
{
    __shared__ float sD[SCHK][SCH];
    __shared__ float sX[SCHK][SCH];
    __shared__ float sZ[SCHK][SCH];
    __shared__ float sB[SCHK][DSTATE];
    __shared__ float sC[SCHK][DSTATE];
    __shared__ unsigned sY[SCHK][SCH];

    const int tid = threadIdx.x;
    const int ch  = tid >> 4;          // channel-local 0..15
    const int n   = tid & 15;          // state 0..15
    const int b   = blockIdx.x >> 7;   // 128 blocks per batch
    const int d0  = (blockIdx.x & 127) * SCH;

    const int lrow = tid >> 4;
    const int lcol = tid & 15;

    const float An = -__expf(A_log[(d0 + ch) * DSTATE + n]);
    const float Dd = Dp[d0 + ch];

    const size_t rowD = (size_t)DINNER;

    float rD, rX, rZ, rB, rC;
    auto issue_loads = [&](int j) {
        const size_t m = (size_t)b * LSEQ + j * SCHK + lrow;
        rD = delta[m * rowD + d0 + lcol];
        rX = xsc  [m * rowD + d0 + lcol];
        rZ = xz   [m * NXZ + DINNER + d0 + lcol];
        rB = dbc  [m * NDBC + DTRANK + lcol];
        rC = dbc  [m * NDBC + DTRANK + DSTATE + lcol];
    };

    // prologue: chunk 0 into smem
    issue_loads(0);
    sD[lrow][lcol] = rD; sX[lrow][lcol] = rX; sZ[lrow][lcol] = rZ;
    sB[lrow][lcol] = rB; sC[lrow][lcol] = rC;
    __syncthreads();

    float h = 0.f;
    const int nchk = LSEQ / SCHK;   // 64
    for (int j = 0; j < nchk; j++) {
        if (j + 1 < nchk) issue_loads(j + 1);   // LDGs overlap compute below

        // phase 1: precompute dA, dBx (independent of h -> fully pipelined)
        float dA[SCHK], dBx[SCHK], hC[SCHK];
#pragma unroll
        for (int s = 0; s < SCHK; s++) {
            const float dl = sD[s][ch];
            const float xv = sX[s][ch];
            dA[s]  = __expf(dl * An);
            dBx[s] = dl * xv * sB[s][n];
        }

        // phase 2: serial recurrence — critical path is 16 fmas
#pragma unroll
        for (int s = 0; s < SCHK; s++) {
            h = fmaf(dA[s], h, dBx[s]);
            hC[s] = h * sC[s][n];
        }

        // phase 3: 16 independent shuffle reductions (pipelined)
#pragma unroll
        for (int s = 0; s < SCHK; s++) {
            float part = hC[s];
            part += __shfl_xor_sync(0xffffffffu, part, 8, 16);
            part += __shfl_xor_sync(0xffffffffu, part, 4, 16);
            part += __shfl_xor_sync(0xffffffffu, part, 2, 16);
            part += __shfl_xor_sync(0xffffffffu, part, 1, 16);

            if (n == 0) {
                const float yv = part + Dd * sX[s][ch];
                const float zv = sZ[s][ch];
                const float sz = zv / (1.f + __expf(-zv));
                sY[s][ch] = f2tf32(yv * sz);
            }
        }
        __syncthreads();   // sY complete; smem tiles free for reuse

        // coalesced output of chunk j
        {
            const size_t m = (size_t)b * LSEQ + j * SCHK + lrow;
            yt[m * rowD + d0 + lcol] = sY[lrow][lcol];
        }

        if (j + 1 < nchk) {
            sD[lrow][lcol] = rD; sX[lrow][lcol] = rX; sZ[lrow][lcol] = rZ;
            sB[lrow][lcol] = rB; sC[lrow][lcol] = rC;
        }
        __syncthreads();
    }
}

// ---------------------------------------------------------------------------
// Launch
// ---------------------------------------------------------------------------
extern "C" void kernel_launch(void* const* d_in, const int* in_sizes, int n_in,
                              void* d_out, int out_size)
{
    const float* x         = (const float*)d_in[0];
    const float* in_proj_w = (const float*)d_in[1];
    const float* conv_w    = (const float*)d_in[2];
    const float* conv_b    = (const float*)d_in[3];
    const float* x_proj_w  = (const float*)d_in[4];
    const float* dt_proj_w = (const float*)d_in[5];
    const float* dt_proj_b = (const float*)d_in[6];
    const float* A_log     = (const float*)d_in[7];
    const float* Dvec      = (const float*)d_in[8];
    const float* out_proj_w= (const float*)d_in[9];
    float* out = (float*)d_out;

    float *xz, *xsc, *dbc_part, *dbc, *delta, *opart;
    unsigned *xt, *wt_in, *wt_out, *yt;
    cudaGetSymbolAddress((void**)&xz,       g_xz);
    cudaGetSymbolAddress((void**)&xsc,      g_xsc);
    cudaGetSymbolAddress((void**)&dbc_part, g_dbc_part);
    cudaGetSymbolAddress((void**)&dbc,      g_dbc);
    cudaGetSymbolAddress((void**)&delta,    g_delta);
    cudaGetSymbolAddress((void**)&xt,       g_xt);
    cudaGetSymbolAddress((void**)&wt_in,    g_wt_in);
    cudaGetSymbolAddress((void**)&wt_out,   g_wt_out);
    cudaGetSymbolAddress((void**)&yt,       g_yt);
    cudaGetSymbolAddress((void**)&opart,    g_opart);

    // 0) pre-convert fp32 -> tf32 (one fused launch)
    {
        const int na4 = (MROWS * DMODEL) / 4;
        const int nb4 = (NXZ * DMODEL) / 4;
        const int nc4 = (DMODEL * DINNER) / 4;
        const int tot = na4 + nb4 + nc4;
        cvt3_tf32_kernel<<<(tot + 255) / 256, 256>>>(
            (const float4*)x, (uint4*)xt, na4,
            (const float4*)in_proj_w, (uint4*)wt_in, nb4,
            (const float4*)out_proj_w, (uint4*)wt_out, nc4);
    }

    // 1) xz = x @ in_proj_w^T  (2048 x 4096, K=1024)  — tcgen05 TF32
    {
        dim3 grid(NXZ / 128, MROWS / 128, 1);
        tgemm_tc<<<grid, 128>>>(xt, wt_in, xz, DMODEL, DMODEL, NXZ,
                                DMODEL, 0);
    }

    // 2) depthwise conv + bias + silu -> xsc
    {
        int n = MROWS * DINNER;
        conv_silu_kernel<<<(n + 255) / 256, 256>>>(xz, conv_w, conv_b, xsc);
    }

    // 3) dbc = xsc @ x_proj_w^T  (2048 x 96, K=2048), fp32, split-K=16
    {
        dim3 grid(1, MROWS / 128, SPLITK_XPROJ);
        sgemm128<0><<<grid, 256>>>(xsc, x_proj_w, dbc_part,
                                   MROWS, NDBC, DINNER,
                                   DINNER, DINNER, NDBC, DINNER / SPLITK_XPROJ,
                                   nullptr);
        int n = MROWS * NDBC;
        reduce_dbc_kernel<<<(n + 255) / 256, 256>>>(dbc_part, dbc);
    }

    // 4) delta = softplus(dbc[:, :64] @ dt_proj_w^T + dt_proj_b)  fp32
    {
        dim3 grid(DINNER / 128, MROWS / 128, 1);
        sgemm128<1><<<grid, 256>>>(dbc, dt_proj_w, delta,
                                   MROWS, DINNER, DTRANK,
                                   NDBC, DTRANK, DINNER, DTRANK, dt_proj_b);
    }

    // 5) selective scan v3 -> yt (tf32)
    {
        int blocks = (BSZ * DINNER) / SCH;   // 256
        scan_kernel<<<blocks, 256>>>(delta, xsc, dbc, xz, A_log, Dvec, yt);
    }

    // 6) out = y @ out_proj_w^T  (2048 x 1024, K=2048) — tcgen05 TF32, split-K=2
    {
        dim3 grid(DMODEL / 128, MROWS / 128, SPLITK_OPROJ);
        tgemm_tc<<<grid, 128>>>(yt, wt_out, opart, DINNER, DINNER, DMODEL,
                                DINNER / SPLITK_OPROJ,
                                (size_t)MROWS * DMODEL);
        int n = MROWS * DMODEL;
        reduce_out_kernel<<<(n + 255) / 256, 256>>>(opart, out);
    }
}

// round 12
// speedup vs baseline: 2.9294x; 1.0748x over previous
#include <cuda_runtime.h>
#include <cuda_bf16.h>
#include <math.h>
#include <stdint.h>

// ---------------------------------------------------------------------------
// Problem constants
// ---------------------------------------------------------------------------
#define BSZ     2
#define LSEQ    1024
#define DMODEL  1024
#define DINNER  2048
#define DSTATE  16
#define DTRANK  64
#define MROWS   (BSZ * LSEQ)        // 2048
#define NXZ     (2 * DINNER)        // 4096
#define NDBC    (DTRANK + 2*DSTATE) // 96
#define NDBC_PAD 128
#define SPLITK_XPROJ 16
#define SPLITK_OPROJ 2

// tcgen05 is only legal on arch-specific ("a") targets. The harness also
// compiles a plain compute_103/sm_103 pass; give that pass an mma.sync path.
#if defined(__CUDA_ARCH_FEAT_SM103_ALL) || defined(__CUDA_ARCH_FEAT_SM100_ALL) || defined(__CUDA_ARCH_FEAT_SM101_ALL)
#define HAS_TCGEN05 1
#else
#define HAS_TCGEN05 0
#endif

// ---------------------------------------------------------------------------
// Scratch (static device memory; no allocations allowed)
// ---------------------------------------------------------------------------
__device__ float    g_xz[MROWS * NXZ];                       // (xs | z)
__device__ float    g_xsc[MROWS * DINNER];                   // conv+silu (fp32)
__device__ unsigned g_xsc_t[MROWS * DINNER];                 // conv+silu (tf32)
__device__ float    g_dbc_part[SPLITK_XPROJ * MROWS * NDBC_PAD];
__device__ float    g_dbc[MROWS * NDBC];
__device__ float    g_delta[MROWS * DINNER];
__device__ unsigned g_xt[MROWS * DMODEL];                    // x in tf32
__device__ unsigned g_wt_in[NXZ * DMODEL];                   // in_proj_w tf32
__device__ unsigned g_wt_out[DMODEL * DINNER];               // out_proj_w tf32
__device__ unsigned g_wt_xp[NDBC_PAD * DINNER];              // x_proj_w tf32 padded
__device__ unsigned g_yt[MROWS * DINNER];                    // scan output tf32
__device__ float    g_opart[SPLITK_OPROJ * MROWS * DMODEL];  // out_proj partials

// ---------------------------------------------------------------------------
// Small PTX helpers
// ---------------------------------------------------------------------------
__device__ __forceinline__ unsigned f2tf32(float x) {
    unsigned r;
    asm("cvt.rna.tf32.f32 %0, %1;" : "=r"(r) : "f"(x));
    return r;
}

__device__ __forceinline__ uint32_t smem_u32(const void* p) {
    uint32_t a;
    asm("{ .reg .u64 t; cvta.to.shared.u64 t, %1; cvt.u32.u64 %0, t; }"
        : "=r"(a) : "l"(p));
    return a;
}

__device__ __forceinline__ void cp_async16(uint32_t smem_addr, const void* gptr) {
    asm volatile("cp.async.cg.shared.global [%0], [%1], 16;"
                 :: "r"(smem_addr), "l"(gptr) : "memory");
}
__device__ __forceinline__ void cp_async_commit() {
    asm volatile("cp.async.commit_group;" ::: "memory");
}
__device__ __forceinline__ void cp_async_wait_all() {
    asm volatile("cp.async.wait_group 0;" ::: "memory");
}

#if HAS_TCGEN05
__device__ __forceinline__ uint32_t elect_one() {
    uint32_t pred;
    asm volatile("{\n .reg .pred p;\n elect.sync _|p, 0xFFFFFFFF;\n"
                 " selp.b32 %0, 1, 0, p;\n}" : "=r"(pred));
    return pred;
}

__device__ __forceinline__ void mbar_init(uint32_t addr, uint32_t cnt) {
    asm volatile("mbarrier.init.shared.b64 [%0], %1;" :: "r"(addr), "r"(cnt) : "memory");
}
__device__ __forceinline__ void mbar_inval(uint32_t addr) {
    asm volatile("mbarrier.inval.shared.b64 [%0];" :: "r"(addr) : "memory");
}
__device__ __forceinline__ void mbar_wait_parity(uint32_t addr, uint32_t parity) {
    asm volatile(
        "{\n .reg .pred P;\n"
        "WAIT_%=:\n"
        " mbarrier.try_wait.parity.acquire.cta.shared::cta.b64 P, [%0], %1, 0x989680;\n"
        " @P bra.uni DONE_%=;\n"
        " bra.uni WAIT_%=;\n"
        "DONE_%=:\n}"
        :: "r"(addr), "r"(parity) : "memory");
}

// 64-bit SMEM matrix descriptor: SW128, Blackwell, LBO=1, SBO=64
__device__ __forceinline__ uint64_t smem_desc_sw128(uint32_t addr) {
    const uint64_t base =
        (uint64_t(2) << 61) | (uint64_t(1) << 46) |
        (uint64_t(64) << 32) | (uint64_t(1) << 16);
    return base | ((uint64_t)(addr >> 4) & 0x3FFF);
}

__device__ __forceinline__ void mma_tf32_ss(uint32_t d_tmem, uint64_t a_desc,
                                            uint64_t b_desc, uint32_t idesc,
                                            uint32_t enable) {
    asm volatile(
        "{\n .reg .pred p;\n"
        " setp.ne.u32 p, %5, 0;\n"
        " tcgen05.mma.cta_group::1.kind::tf32 [%0], %1, %2, %3, {%4, %4, %4, %4}, p;\n"
        "}"
        :: "r"(d_tmem), "l"(a_desc), "l"(b_desc), "r"(idesc), "r"(0u), "r"(enable)
        : "memory");
}
#else
__device__ __forceinline__ void mma_m16n8k8_tf32(float c[4], const unsigned a[4],
                                                 const unsigned b[2]) {
    asm volatile(
        "mma.sync.aligned.m16n8k8.row.col.f32.tf32.tf32.f32 "
        "{%0,%1,%2,%3}, {%4,%5,%6,%7}, {%8,%9}, {%0,%1,%2,%3};\n"
        : "+f"(c[0]), "+f"(c[1]), "+f"(c[2]), "+f"(c[3])
        : "r"(a[0]), "r"(a[1]), "r"(a[2]), "r"(a[3]), "r"(b[0]), "r"(b[1]));
}
#endif

// ---------------------------------------------------------------------------
// Fused fp32 -> tf32(rna) conversion of the four GEMM operands (one launch).
// x_proj_w is padded from 96 to 128 rows with zeros.
// ---------------------------------------------------------------------------
__global__ void cvt4_tf32_kernel(const float4* __restrict__ a, uint4* __restrict__ oa, int na4,
                                 const float4* __restrict__ b, uint4* __restrict__ ob, int nb4,
                                 const float4* __restrict__ c, uint4* __restrict__ oc, int nc4,
                                 const float4* __restrict__ xp, uint4* __restrict__ oxp, int nx4)
{
    int i = blockIdx.x * blockDim.x + threadIdx.x;
    if (i < na4) {
        float4 v = a[i];
        oa[i] = make_uint4(f2tf32(v.x), f2tf32(v.y), f2tf32(v.z), f2tf32(v.w));
        return;
    }
    i -= na4;
    if (i < nb4) {
        float4 v = b[i];
        ob[i] = make_uint4(f2tf32(v.x), f2tf32(v.y), f2tf32(v.z), f2tf32(v.w));
        return;
    }
    i -= nb4;
    if (i < nc4) {
        float4 v = c[i];
        oc[i] = make_uint4(f2tf32(v.x), f2tf32(v.y), f2tf32(v.z), f2tf32(v.w));
        return;
    }
    i -= nc4;
    if (i < nx4) {
        // dest is [128][2048] tf32; rows >= 96 are zero padding
        const int row = (i * 4) / DINNER;
        if (row < NDBC) {
            float4 v = xp[i];
            oxp[i] = make_uint4(f2tf32(v.x), f2tf32(v.y), f2tf32(v.z), f2tf32(v.w));
        } else {
            oxp[i] = make_uint4(0u, 0u, 0u, 0u);
        }
    }
}

// ---------------------------------------------------------------------------
// TF32 tensor GEMM on PRE-CONVERTED tf32 inputs, with optional split-K:
// blockIdx.z takes K-chunk [z*kChunk, (z+1)*kChunk) and writes to
// C + z*splitStride. C[m,n] = sum_k A[m,k]*B[n,k].
// Requires M%128==0, N%128==0, kChunk%32==0, lda/ldb%4==0.
// ---------------------------------------------------------------------------
__global__ void __launch_bounds__(128, 4) tgemm_tc(
    const unsigned* __restrict__ A, const unsigned* __restrict__ B,
    float* __restrict__ C, int lda, int ldb, int ldc,
    int kChunk, size_t splitStride)
{
    __shared__ __align__(1024) unsigned As[128 * 32];   // 16 KB
    __shared__ __align__(1024) unsigned Bs[128 * 32];   // 16 KB
#if HAS_TCGEN05
    __shared__ __align__(8) unsigned long long mbar_s;
    __shared__ unsigned tptr_s;
#endif

    const int tid = threadIdx.x;
    const int wid = tid >> 5, lane = tid & 31;
    const int bm = blockIdx.y * 128;
    const int bn = blockIdx.x * 128;
    const int kBegin = blockIdx.z * kChunk;
    C += (size_t)blockIdx.z * splitStride;

    const int r0 = tid >> 3;      // 0..15
    const int c4 = tid & 7;       // 0..7

    const unsigned* Ap = A + (size_t)(bm + r0) * lda + c4 * 4 + kBegin;
    const unsigned* Bp = B + (size_t)(bn + r0) * ldb + c4 * 4 + kBegin;
    const int nch = kChunk / 32;

    const uint32_t s_as = smem_u32(As);
    const uint32_t s_bs = smem_u32(Bs);

#if HAS_TCGEN05
    const uint32_t s_mbar = smem_u32(&mbar_s);
    const uint32_t s_tptr = smem_u32(&tptr_s);

    if (wid == 0) {
        asm volatile("tcgen05.alloc.cta_group::1.sync.aligned.shared::cta.b32 [%0], %1;"
                     :: "r"(s_tptr), "r"(128u) : "memory");
        asm volatile("tcgen05.relinquish_alloc_permit.cta_group::1.sync.aligned;");
    }
    if (tid == 0) mbar_init(s_mbar, 1);
    __syncthreads();

    uint32_t tmem;
    asm volatile("ld.shared.b32 %0, [%1];" : "=r"(tmem) : "r"(s_tptr));

    const uint32_t idesc = (1u << 4) | (2u << 7) | (2u << 10) |
                           ((128u / 8) << 17) | ((128u / 16) << 24);

    const uint64_t adesc0 = smem_desc_sw128(s_as);
    const uint64_t bdesc0 = smem_desc_sw128(s_bs);
    const bool leader = (wid == 0) && elect_one();

    for (int c = 0; c < nch; c++) {
        if (c > 0) mbar_wait_parity(s_mbar, (c - 1) & 1);

#pragma unroll
        for (int i = 0; i < 8; i++) {
            const int row = r0 + i * 16;
            unsigned off = row * 128 + c4 * 16;
            unsigned sw = off ^ ((off >> 3) & 0x70);
            cp_async16(s_as + sw, Ap + (size_t)(i * 16) * lda + c * 32);
            cp_async16(s_bs + sw, Bp + (size_t)(i * 16) * ldb + c * 32);
        }
        cp_async_commit();
        cp_async_wait_all();
        asm volatile("fence.proxy.async.shared::cta;" ::: "memory");
        __syncthreads();

        if (leader) {
#pragma unroll
            for (int ks = 0; ks < 4; ks++) {
                mma_tf32_ss(tmem, adesc0 + ks * 2, bdesc0 + ks * 2, idesc,
                            (c > 0 || ks > 0) ? 1u : 0u);
            }
            asm volatile(
                "tcgen05.commit.cta_group::1.mbarrier::arrive::one.shared::cluster.b64 [%0];"
                :: "r"(s_mbar) : "memory");
        }
    }

    mbar_wait_parity(s_mbar, (nch - 1) & 1);
    asm volatile("tcgen05.fence::after_thread_sync;" ::: "memory");

    const int row = bm + wid * 32 + lane;
    float* Crow = C + (size_t)row * ldc + bn;
#pragma unroll
    for (int g = 0; g < 4; g++) {
        uint32_t d[32];
        asm volatile(
            "tcgen05.ld.sync.aligned.32x32b.x32.b32 "
            "{%0,%1,%2,%3,%4,%5,%6,%7,%8,%9,%10,%11,%12,%13,%14,%15,"
            "%16,%17,%18,%19,%20,%21,%22,%23,%24,%25,%26,%27,%28,%29,%30,%31}, [%32];"
            : "=r"(d[0]), "=r"(d[1]), "=r"(d[2]), "=r"(d[3]),
              "=r"(d[4]), "=r"(d[5]), "=r"(d[6]), "=r"(d[7]),
              "=r"(d[8]), "=r"(d[9]), "=r"(d[10]), "=r"(d[11]),
              "=r"(d[12]), "=r"(d[13]), "=r"(d[14]), "=r"(d[15]),
              "=r"(d[16]), "=r"(d[17]), "=r"(d[18]), "=r"(d[19]),
              "=r"(d[20]), "=r"(d[21]), "=r"(d[22]), "=r"(d[23]),
              "=r"(d[24]), "=r"(d[25]), "=r"(d[26]), "=r"(d[27]),
              "=r"(d[28]), "=r"(d[29]), "=r"(d[30]), "=r"(d[31])
            : "r"(tmem + g * 32));
        asm volatile("tcgen05.wait::ld.sync.aligned;" ::: "memory");
#pragma unroll
        for (int v = 0; v < 8; v++) {
            *(float4*)(Crow + g * 32 + v * 4) = make_float4(
                __uint_as_float(d[v * 4 + 0]), __uint_as_float(d[v * 4 + 1]),
                __uint_as_float(d[v * 4 + 2]), __uint_as_float(d[v * 4 + 3]));
        }
    }

    __syncthreads();
    if (tid == 0) mbar_inval(s_mbar);
    __syncthreads();
    if (wid == 0) {
        asm volatile("tcgen05.dealloc.cta_group::1.sync.aligned.b32 %0, %1;"
                     :: "r"(tmem), "r"(128u));
    }
#else
    const int wm = wid * 32;
    const int q = lane & 3;
    const int r = lane >> 2;

    float acc[2][16][4];
#pragma unroll
    for (int i = 0; i < 2; i++)
#pragma unroll
        for (int j = 0; j < 16; j++)
#pragma unroll
            for (int t = 0; t < 4; t++) acc[i][j][t] = 0.f;

    for (int c = 0; c < nch; c++) {
        __syncthreads();
#pragma unroll
        for (int i = 0; i < 8; i++) {
            const int row = r0 + i * 16;
            uint4 av = *(const uint4*)(Ap + (size_t)(i * 16) * lda + c * 32);
            uint4 bv = *(const uint4*)(Bp + (size_t)(i * 16) * ldb + c * 32);
            *(uint4*)&As[row * 32 + c4 * 4] = av;
            *(uint4*)&Bs[row * 32 + c4 * 4] = bv;
        }
        __syncthreads();

#pragma unroll
        for (int kk = 0; kk < 32; kk += 8) {
            unsigned af[2][4];
#pragma unroll
            for (int i = 0; i < 2; i++) {
                const int mrow = wm + i * 16;
                af[i][0] = As[(mrow + r) * 32 + kk + q];
                af[i][1] = As[(mrow + r + 8) * 32 + kk + q];
                af[i][2] = As[(mrow + r) * 32 + kk + q + 4];
                af[i][3] = As[(mrow + r + 8) * 32 + kk + q + 4];
            }
#pragma unroll
            for (int j = 0; j < 16; j++) {
                unsigned bf[2];
                bf[0] = Bs[(j * 8 + r) * 32 + kk + q];
                bf[1] = Bs[(j * 8 + r) * 32 + kk + q + 4];
#pragma unroll
                for (int i = 0; i < 2; i++)
                    mma_m16n8k8_tf32(acc[i][j], af[i], bf);
            }
        }
    }

#pragma unroll
    for (int i = 0; i < 2; i++) {
        const int row = bm + wm + i * 16 + r;
#pragma unroll
        for (int j = 0; j < 16; j++) {
            const int col = bn + j * 8 + q * 2;
            *(float2*)&C[(size_t)row * ldc + col] =
                make_float2(acc[i][j][0], acc[i][j][1]);
            *(float2*)&C[(size_t)(row + 8) * ldc + col] =
                make_float2(acc[i][j][2], acc[i][j][3]);
        }
    }
#endif
}

// ---------------------------------------------------------------------------
// FP32 SGEMM for the dt_proj GEMM (delta precision before exp).
// EPI: 1 = softplus(x + bias[col]).
// ---------------------------------------------------------------------------
template<int EPI>
__global__ void __launch_bounds__(256, 2) sgemm128(
    const float* __restrict__ A, const float* __restrict__ B,
    float* __restrict__ C, int M, int N, int K,
    int lda, int ldb, int ldc, int kChunk,
    const float* __restrict__ bias)
{
    __shared__ float As[8][128];
    __shared__ float Bs[8][128];

    const int tid = threadIdx.x;
    const int bm = blockIdx.y * 128;
    const int bn = blockIdx.x * 128;
    int kBegin = blockIdx.z * kChunk;
    int kEnd   = kBegin + kChunk; if (kEnd > K) kEnd = K;
    C += (size_t)blockIdx.z * (size_t)M * (size_t)ldc;

    const int ar = tid >> 1;
    const int ac = (tid & 1) * 4;
    const int ty = tid >> 4;
    const int tx = tid & 15;

    float acc[8][8];
#pragma unroll
    for (int i = 0; i < 8; i++)
#pragma unroll
        for (int j = 0; j < 8; j++) acc[i][j] = 0.f;

    const float* Aptr = A + (size_t)(bm + ar) * lda + ac;
    const int brow = bn + ar;
    const float* Bptr = B + (size_t)brow * ldb + ac;
    const bool bvalid = (brow < N);

    for (int k0 = kBegin; k0 < kEnd; k0 += 8) {
        float4 av = *(const float4*)(Aptr + k0);
        float4 bv = make_float4(0.f, 0.f, 0.f, 0.f);
        if (bvalid) bv = *(const float4*)(Bptr + k0);

        __syncthreads();
        As[ac + 0][ar] = av.x; As[ac + 1][ar] = av.y;
        As[ac + 2][ar] = av.z; As[ac + 3][ar] = av.w;
        Bs[ac + 0][ar] = bv.x; Bs[ac + 1][ar] = bv.y;
        Bs[ac + 2][ar] = bv.z; Bs[ac + 3][ar] = bv.w;
        __syncthreads();

#pragma unroll
        for (int kk = 0; kk < 8; kk++) {
            float a[8], b[8];
#pragma unroll
            for (int i = 0; i < 8; i++) a[i] = As[kk][ty * 8 + i];
#pragma unroll
            for (int j = 0; j < 8; j++) b[j] = Bs[kk][tx * 8 + j];
#pragma unroll
            for (int i = 0; i < 8; i++)
#pragma unroll
                for (int j = 0; j < 8; j++)
                    acc[i][j] = fmaf(a[i], b[j], acc[i][j]);
        }
    }

#pragma unroll
    for (int i = 0; i < 8; i++) {
        const int row = bm + ty * 8 + i;
#pragma unroll
        for (int j = 0; j < 8; j++) {
            const int col = bn + tx * 8 + j;
            if (col < N) {
                float v = acc[i][j];
                if (EPI == 1) {
                    v += bias[col];
                    v = fmaxf(v, 0.f) + log1pf(__expf(-fabsf(v)));
                }
                C[(size_t)row * ldc + col] = v;
            }
        }
    }
}

// ---------------------------------------------------------------------------
// Depthwise causal conv (k=4) + bias + SiLU — dual fp32/tf32 output
// ---------------------------------------------------------------------------
__global__ void conv_silu_kernel(const float* __restrict__ xz,
                                 const float* __restrict__ cw,
                                 const float* __restrict__ cb,
                                 float* __restrict__ xsc,
                                 unsigned* __restrict__ xsc_t)
{
    const int idx = blockIdx.x * blockDim.x + threadIdx.x;
    if (idx >= MROWS * DINNER) return;
    const int d = idx & (DINNER - 1);
    const int m = idx >> 11;
    const int l = m & (LSEQ - 1);

    const float w0 = cw[d * 4 + 0], w1 = cw[d * 4 + 1];
    const float w2 = cw[d * 4 + 2], w3 = cw[d * 4 + 3];
    const float* p = xz + (size_t)m * NXZ + d;

    float acc = cb[d] + w3 * p[0];
    if (l >= 1) acc = fmaf(w2, p[-NXZ],     acc);
    if (l >= 2) acc = fmaf(w1, p[-2 * NXZ], acc);
    if (l >= 3) acc = fmaf(w0, p[-3 * NXZ], acc);

    const float v = acc / (1.f + __expf(-acc));
    xsc[idx] = v;
    xsc_t[idx] = f2tf32(v);
}

// ---------------------------------------------------------------------------
// Split-K reductions
// ---------------------------------------------------------------------------
__global__ void reduce_dbc_kernel(const float* __restrict__ part,
                                  float* __restrict__ out)
{
    const int idx = blockIdx.x * blockDim.x + threadIdx.x;
    if (idx >= MROWS * NDBC) return;
    const int row = idx / NDBC;
    const int col = idx - row * NDBC;
    float s = 0.f;
#pragma unroll
    for (int j = 0; j < SPLITK_XPROJ; j++)
        s += part[(size_t)j * MROWS * NDBC_PAD + (size_t)row * NDBC_PAD + col];
    out[idx] = s;
}

__global__ void reduce_out_kernel(const float* __restrict__ part,
                                  float* __restrict__ out)
{
    const int idx = blockIdx.x * blockDim.x + threadIdx.x;
    if (idx >= MROWS * DMODEL) return;
    out[idx] = part[idx] + part[(size_t)MROWS * DMODEL + idx];
}

// ---------------------------------------------------------------------------
// Selective scan v3 (phase-split recurrence; see R11)
// ---------------------------------------------------------------------------
#define SCH   16   // channels per CTA
#define SCHK  16   // l-steps per chunk

__global__ void __launch_bounds__(256) scan_kernel(
    const float* __restrict__ delta,
    const float* __restrict__ xsc,
    const float* __restrict__ dbc,
    const float* __restrict__ xz,
    const float* __restrict__ A_log,
    const float* __restrict__ Dp,
    unsigned* __restrict__ yt)
{
    __shared__ float sD[SCHK][SCH];
    __shared__ float sX[SCHK][SCH];
    __shared__ float sZ[SCHK][SCH];
    __shared__ float sB[SCHK][DSTATE];
    __shared__ float sC[SCHK][DSTATE];
    __shared__ unsigned sY[SCHK][SCH];

    const int tid = threadIdx.x;
    const int ch  = tid >> 4;          // channel-local 0..15
    const int n   = tid & 15;          // state 0..15
    const int b   = blockIdx.x >> 7;   // 128 blocks per batch
    const int d0  = (blockIdx.x & 127) * SCH;

    const int lrow = tid >> 4;
    const int lcol = tid & 15;

    const float An = -__expf(A_log[(d0 + ch) * DSTATE + n]);
    const float Dd = Dp[d0 + ch];

    const size_t rowD = (size_t)DINNER;

    float rD, rX, rZ, rB, rC;
    auto issue_loads = [&](int j) {
        const size_t m = (size_t)b * LSEQ + j * SCHK + lrow;
        rD = delta[m * rowD + d0 + lcol];
        rX = xsc  [m * rowD + d0 + lcol];
        rZ = xz   [m * NXZ + DINNER + d0 + lcol];
        rB = dbc  [m * NDBC + DTRANK + lcol];
        rC = dbc  [m * NDBC + DTRANK + DSTATE + lcol];
    };

    issue_loads(0);
    sD[lrow][lcol] = rD; sX[lrow][lcol] = rX; sZ[lrow][lcol] = rZ;
    sB[lrow][lcol] = rB; sC[lrow][lcol] = rC;
    __syncthreads();

    float h = 0.f;
    const int nchk = LSEQ / SCHK;   // 64
    for (int j = 0; j < nchk; j++) {
        if (j + 1 < nchk) issue_loads(j + 1);

        float dA[SCHK], dBx[SCHK], hC[SCHK];
#pragma unroll
        for (int s = 0; s < SCHK; s++) {
            const float dl = sD[s][ch];
            const float xv = sX[s][ch];
            dA[s]  = __expf(dl * An);
            dBx[s] = dl * xv * sB[s][n];
        }

#pragma unroll
        for (int s = 0; s < SCHK; s++) {
            h = fmaf(dA[s], h, dBx[s]);
            hC[s] = h * sC[s][n];
        }

#pragma unroll
        for (int s = 0; s < SCHK; s++) {
            float part = hC[s];
            part += __shfl_xor_sync(0xffffffffu, part, 8, 16);
            part += __shfl_xor_sync(0xffffffffu, part, 4, 16);
            part += __shfl_xor_sync(0xffffffffu, part, 2, 16);
            part += __shfl_xor_sync(0xffffffffu, part, 1, 16);

            if (n == 0) {
                const float yv = part + Dd * sX[s][ch];
                const float zv = sZ[s][ch];
                const float sz = zv / (1.f + __expf(-zv));
                sY[s][ch] = f2tf32(yv * sz);
            }
        }
        __syncthreads();

        {
            const size_t m = (size_t)b * LSEQ + j * SCHK + lrow;
            yt[m * rowD + d0 + lcol] = sY[lrow][lcol];
        }

        if (j + 1 < nchk) {
            sD[lrow][lcol] = rD; sX[lrow][lcol] = rX; sZ[lrow][lcol] = rZ;
            sB[lrow][lcol] = rB; sC[lrow][lcol] = rC;
        }
        __syncthreads();
    }
}

// ---------------------------------------------------------------------------
// Launch
// ---------------------------------------------------------------------------
extern "C" void kernel_launch(void* const* d_in, const int* in_sizes, int n_in,
                              void* d_out, int out_size)
{
    const float* x         = (const float*)d_in[0];
    const float* in_proj_w = (const float*)d_in[1];
    const float* conv_w    = (const float*)d_in[2];
    const float* conv_b    = (const float*)d_in[3];
    const float* x_proj_w  = (const float*)d_in[4];
    const float* dt_proj_w = (const float*)d_in[5];
    const float* dt_proj_b = (const float*)d_in[6];
    const float* A_log     = (const float*)d_in[7];
    const float* Dvec      = (const float*)d_in[8];
    const float* out_proj_w= (const float*)d_in[9];
    float* out = (float*)d_out;

    float *xz, *xsc, *dbc_part, *dbc, *delta, *opart;
    unsigned *xsc_t, *xt, *wt_in, *wt_out, *wt_xp, *yt;
    cudaGetSymbolAddress((void**)&xz,       g_xz);
    cudaGetSymbolAddress((void**)&xsc,      g_xsc);
    cudaGetSymbolAddress((void**)&xsc_t,    g_xsc_t);
    cudaGetSymbolAddress((void**)&dbc_part, g_dbc_part);
    cudaGetSymbolAddress((void**)&dbc,      g_dbc);
    cudaGetSymbolAddress((void**)&delta,    g_delta);
    cudaGetSymbolAddress((void**)&xt,       g_xt);
    cudaGetSymbolAddress((void**)&wt_in,    g_wt_in);
    cudaGetSymbolAddress((void**)&wt_out,   g_wt_out);
    cudaGetSymbolAddress((void**)&wt_xp,    g_wt_xp);
    cudaGetSymbolAddress((void**)&yt,       g_yt);
    cudaGetSymbolAddress((void**)&opart,    g_opart);

    // 0) pre-convert fp32 -> tf32 (one fused launch; x_proj_w zero-padded)
    {
        const int na4 = (MROWS * DMODEL) / 4;
        const int nb4 = (NXZ * DMODEL) / 4;
        const int nc4 = (DMODEL * DINNER) / 4;
        const int nx4 = (NDBC_PAD * DINNER) / 4;
        const int tot = na4 + nb4 + nc4 + nx4;
        cvt4_tf32_kernel<<<(tot + 255) / 256, 256>>>(
            (const float4*)x, (uint4*)xt, na4,
            (const float4*)in_proj_w, (uint4*)wt_in, nb4,
            (const float4*)out_proj_w, (uint4*)wt_out, nc4,
            (const float4*)x_proj_w, (uint4*)wt_xp, nx4);
    }

    // 1) xz = x @ in_proj_w^T  (2048 x 4096, K=1024)  — tcgen05 TF32
    {
        dim3 grid(NXZ / 128, MROWS / 128, 1);
        tgemm_tc<<<grid, 128>>>(xt, wt_in, xz, DMODEL, DMODEL, NXZ,
                                DMODEL, 0);
    }

    // 2) depthwise conv + bias + silu -> xsc (fp32) + xsc_t (tf32)
    {
        int n = MROWS * DINNER;
        conv_silu_kernel<<<(n + 255) / 256, 256>>>(xz, conv_w, conv_b, xsc, xsc_t);
    }

    // 3) dbc = xsc @ x_proj_w^T  (2048 x 96pad128, K=2048) — tcgen05, split-K=16
    {
        dim3 grid(1, MROWS / 128, SPLITK_XPROJ);
        tgemm_tc<<<grid, 128>>>(xsc_t, wt_xp, dbc_part,
                                DINNER, DINNER, NDBC_PAD,
                                DINNER / SPLITK_XPROJ,
                                (size_t)MROWS * NDBC_PAD);
        int n = MROWS * NDBC;
        reduce_dbc_kernel<<<(n + 255) / 256, 256>>>(dbc_part, dbc);
    }

    // 4) delta = softplus(dbc[:, :64] @ dt_proj_w^T + dt_proj_b)  fp32
    {
        dim3 grid(DINNER / 128, MROWS / 128, 1);
        sgemm128<1><<<grid, 256>>>(dbc, dt_proj_w, delta,
                                   MROWS, DINNER, DTRANK,
                                   NDBC, DTRANK, DINNER, DTRANK, dt_proj_b);
    }

    // 5) selective scan v3 -> yt (tf32)
    {
        int blocks = (BSZ * DINNER) / SCH;   // 256
        scan_kernel<<<blocks, 256>>>(delta, xsc, dbc, xz, A_log, Dvec, yt);
    }

    // 6) out = y @ out_proj_w^T  (2048 x 1024, K=2048) — tcgen05 TF32, split-K=2
    {
        dim3 grid(DMODEL / 128, MROWS / 128, SPLITK_OPROJ);
        tgemm_tc<<<grid, 128>>>(yt, wt_out, opart, DINNER, DINNER, DMODEL,
                                DINNER / SPLITK_OPROJ,
                                (size_t)MROWS * DMODEL);
        int n = MROWS * DMODEL;
        reduce_out_kernel<<<(n + 255) / 256, 256>>>(opart, out);
    }
}

// round 16
// speedup vs baseline: 2.9480x; 1.0064x over previous
#include <cuda_runtime.h>
#include <cuda_bf16.h>
#include <math.h>
#include <stdint.h>

// ---------------------------------------------------------------------------
// Problem constants
// ---------------------------------------------------------------------------
#define BSZ     2
#define LSEQ    1024
#define DMODEL  1024
#define DINNER  2048
#define DSTATE  16
#define DTRANK  64
#define MROWS   (BSZ * LSEQ)        // 2048
#define NXZ     (2 * DINNER)        // 4096
#define NDBC    (DTRANK + 2*DSTATE) // 96
#define NDBC_PAD 128
#define SPLITK_XPROJ 16
#define SPLITK_OPROJ 2

// Dynamic smem: 2 stages x (16KB A + 16KB B) + align slack
#define TG_STAGE_BYTES 32768
#define TG_SMEM_BYTES  (2 * TG_STAGE_BYTES + 1024)

// tcgen05 is only legal on arch-specific ("a") targets. The harness also
// compiles a plain compute_103/sm_103 pass; give that pass an mma.sync path.
#if defined(__CUDA_ARCH_FEAT_SM103_ALL) || defined(__CUDA_ARCH_FEAT_SM100_ALL) || defined(__CUDA_ARCH_FEAT_SM101_ALL)
#define HAS_TCGEN05 1
#else
#define HAS_TCGEN05 0
#endif

// ---------------------------------------------------------------------------
// Scratch (static device memory; no allocations allowed)
// ---------------------------------------------------------------------------
__device__ float    g_xz[MROWS * NXZ];                       // (xs | z)
__device__ float    g_xsc[MROWS * DINNER];                   // conv+silu (fp32)
__device__ unsigned g_xsc_t[MROWS * DINNER];                 // conv+silu (tf32)
__device__ float    g_dbc_part[SPLITK_XPROJ * MROWS * NDBC_PAD];
__device__ float    g_dbc[MROWS * NDBC];                     // fp32 (scan)
__device__ unsigned g_dbc_t[MROWS * NDBC];                   // tf32 (dt GEMM)
__device__ float    g_delta[MROWS * DINNER];
__device__ unsigned g_xt[MROWS * DMODEL];                    // x in tf32
__device__ unsigned g_wt_in[NXZ * DMODEL];                   // in_proj_w tf32
__device__ unsigned g_wt_out[DMODEL * DINNER];               // out_proj_w tf32
__device__ unsigned g_wt_xp[NDBC_PAD * DINNER];              // x_proj_w tf32 padded
__device__ unsigned g_wt_dt[DINNER * DTRANK];                // dt_proj_w tf32
__device__ unsigned g_yt[MROWS * DINNER];                    // scan output tf32
__device__ float    g_opart[SPLITK_OPROJ * MROWS * DMODEL];  // out_proj partials

// ---------------------------------------------------------------------------
// Small PTX helpers
// ---------------------------------------------------------------------------
__device__ __forceinline__ unsigned f2tf32(float x) {
    unsigned r;
    asm("cvt.rna.tf32.f32 %0, %1;" : "=r"(r) : "f"(x));
    return r;
}

__device__ __forceinline__ uint32_t smem_u32(const void* p) {
    uint32_t a;
    asm("{ .reg .u64 t; cvta.to.shared.u64 t, %1; cvt.u32.u64 %0, t; }"
        : "=r"(a) : "l"(p));
    return a;
}

__device__ __forceinline__ void cp_async16(uint32_t smem_addr, const void* gptr) {
    asm volatile("cp.async.cg.shared.global [%0], [%1], 16;"
                 :: "r"(smem_addr), "l"(gptr) : "memory");
}
__device__ __forceinline__ void cp_async_commit() {
    asm volatile("cp.async.commit_group;" ::: "memory");
}
__device__ __forceinline__ void cp_async_wait_all() {
    asm volatile("cp.async.wait_group 0;" ::: "memory");
}

#if HAS_TCGEN05
__device__ __forceinline__ uint32_t elect_one() {
    uint32_t pred;
    asm volatile("{\n .reg .pred p;\n elect.sync _|p, 0xFFFFFFFF;\n"
                 " selp.b32 %0, 1, 0, p;\n}" : "=r"(pred));
    return pred;
}

__device__ __forceinline__ void mbar_init(uint32_t addr, uint32_t cnt) {
    asm volatile("mbarrier.init.shared.b64 [%0], %1;" :: "r"(addr), "r"(cnt) : "memory");
}
__device__ __forceinline__ void mbar_inval(uint32_t addr) {
    asm volatile("mbarrier.inval.shared.b64 [%0];" :: "r"(addr) : "memory");
}
__device__ __forceinline__ void mbar_wait_parity(uint32_t addr, uint32_t parity) {
    asm volatile(
        "{\n .reg .pred P;\n"
        "WAIT_%=:\n"
        " mbarrier.try_wait.parity.acquire.cta.shared::cta.b64 P, [%0], %1, 0x989680;\n"
        " @P bra.uni DONE_%=;\n"
        " bra.uni WAIT_%=;\n"
        "DONE_%=:\n}"
        :: "r"(addr), "r"(parity) : "memory");
}

// 64-bit SMEM matrix descriptor: SW128, Blackwell, LBO=1, SBO=64
__device__ __forceinline__ uint64_t smem_desc_sw128(uint32_t addr) {
    const uint64_t base =
        (uint64_t(2) << 61) | (uint64_t(1) << 46) |
        (uint64_t(64) << 32) | (uint64_t(1) << 16);
    return base | ((uint64_t)(addr >> 4) & 0x3FFF);
}

__device__ __forceinline__ void mma_tf32_ss(uint32_t d_tmem, uint64_t a_desc,
                                            uint64_t b_desc, uint32_t idesc,
                                            uint32_t enable) {
    asm volatile(
        "{\n .reg .pred p;\n"
        " setp.ne.u32 p, %5, 0;\n"
        " tcgen05.mma.cta_group::1.kind::tf32 [%0], %1, %2, %3, {%4, %4, %4, %4}, p;\n"
        "}"
        :: "r"(d_tmem), "l"(a_desc), "l"(b_desc), "r"(idesc), "r"(0u), "r"(enable)
        : "memory");
}
#else
__device__ __forceinline__ void mma_m16n8k8_tf32(float c[4], const unsigned a[4],
                                                 const unsigned b[2]) {
    asm volatile(
        "mma.sync.aligned.m16n8k8.row.col.f32.tf32.tf32.f32 "
        "{%0,%1,%2,%3}, {%4,%5,%6,%7}, {%8,%9}, {%0,%1,%2,%3};\n"
        : "+f"(c[0]), "+f"(c[1]), "+f"(c[2]), "+f"(c[3])
        : "r"(a[0]), "r"(a[1]), "r"(a[2]), "r"(a[3]), "r"(b[0]), "r"(b[1]));
}
#endif

// epilogue: optional softplus(x + bias)
__device__ __forceinline__ float epi_apply(float v, const float* bias, int col) {
    if (bias) {
        v += bias[col];
        v = fmaxf(v, 0.f) + log1pf(__expf(-fabsf(v)));
    }
    return v;
}

// ---------------------------------------------------------------------------
// Fused fp32 -> tf32(rna) conversion of the five GEMM operands (one launch).
// x_proj_w is padded from 96 to 128 rows with zeros.
// ---------------------------------------------------------------------------
__global__ void cvt5_tf32_kernel(const float4* __restrict__ a, uint4* __restrict__ oa, int na4,
                                 const float4* __restrict__ b, uint4* __restrict__ ob, int nb4,
                                 const float4* __restrict__ c, uint4* __restrict__ oc, int nc4,
                                 const float4* __restrict__ xp, uint4* __restrict__ oxp, int nx4,
                                 const float4* __restrict__ dt, uint4* __restrict__ odt, int nd4)
{
    int i = blockIdx.x * blockDim.x + threadIdx.x;
    if (i < na4) {
        float4 v = a[i];
        oa[i] = make_uint4(f2tf32(v.x), f2tf32(v.y), f2tf32(v.z), f2tf32(v.w));
        return;
    }
    i -= na4;
    if (i < nb4) {
        float4 v = b[i];
        ob[i] = make_uint4(f2tf32(v.x), f2tf32(v.y), f2tf32(v.z), f2tf32(v.w));
        return;
    }
    i -= nb4;
    if (i < nc4) {
        float4 v = c[i];
        oc[i] = make_uint4(f2tf32(v.x), f2tf32(v.y), f2tf32(v.z), f2tf32(v.w));
        return;
    }
    i -= nc4;
    if (i < nx4) {
        const int row = (i * 4) / DINNER;
        if (row < NDBC) {
            float4 v = xp[i];
            oxp[i] = make_uint4(f2tf32(v.x), f2tf32(v.y), f2tf32(v.z), f2tf32(v.w));
        } else {
            oxp[i] = make_uint4(0u, 0u, 0u, 0u);
        }
        return;
    }
    i -= nx4;
    if (i < nd4) {
        float4 v = dt[i];
        odt[i] = make_uint4(f2tf32(v.x), f2tf32(v.y), f2tf32(v.z), f2tf32(v.w));
    }
}

// ---------------------------------------------------------------------------
// TF32 tensor GEMM, double-buffered cp.async pipeline:
// loads of chunk c+1 overlap the tcgen05 MMA of chunk c. Per-stage mbarriers
// with in-order phase counters (no parity aliasing; commit to mbar[c&1],
// reuse of a stage waits its barrier's next phase).
// Optional split-K (blockIdx.z) and softplus+bias epilogue (bias != nullptr).
// C[m,n] = sum_k A[m,k]*B[n,k]. M%128==0, N%128==0, kChunk%32==0, lda/ldb%4==0.
// ---------------------------------------------------------------------------
__global__ void __launch_bounds__(128) tgemm_tc(
    const unsigned* __restrict__ A, const unsigned* __restrict__ B,
    float* __restrict__ C, int lda, int ldb, int ldc,
    int kChunk, size_t splitStride, const float* __restrict__ bias)
{
    extern __shared__ unsigned dynbuf[];
#if HAS_TCGEN05
    __shared__ __align__(8) unsigned long long mbar_s[2];
    __shared__ unsigned tptr_s;
#endif

    const int tid = threadIdx.x;
    const int wid = tid >> 5, lane = tid & 31;
    const int bm = blockIdx.y * 128;
    const int bn = blockIdx.x * 128;
    const int kBegin = blockIdx.z * kChunk;
    C += (size_t)blockIdx.z * splitStride;

    // 1024B-aligned stage base
    const uint32_t sbase = smem_u32(dynbuf);
    const uint32_t salign = (sbase + 1023u) & ~1023u;

    const int r0 = tid >> 3;      // 0..15
    const int c4 = tid & 7;       // 0..7

    const unsigned* Ap = A + (size_t)(bm + r0) * lda + c4 * 4 + kBegin;
    const unsigned* Bp = B + (size_t)(bn + r0) * ldb + c4 * 4 + kBegin;
    const int nch = kChunk / 32;

#if HAS_TCGEN05
    const uint32_t s_mbar0 = smem_u32(&mbar_s[0]);
    const uint32_t s_mbar1 = smem_u32(&mbar_s[1]);
    const uint32_t s_tptr  = smem_u32(&tptr_s);

    if (wid == 0) {
        asm volatile("tcgen05.alloc.cta_group::1.sync.aligned.shared::cta.b32 [%0], %1;"
                     :: "r"(s_tptr), "r"(128u) : "memory");
        asm volatile("tcgen05.relinquish_alloc_permit.cta_group::1.sync.aligned;");
    }
    if (tid == 0) { mbar_init(s_mbar0, 1); mbar_init(s_mbar1, 1); }
    __syncthreads();

    uint32_t tmem;
    asm volatile("ld.shared.b32 %0, [%1];" : "=r"(tmem) : "r"(s_tptr));

    const uint32_t idesc = (1u << 4) | (2u << 7) | (2u << 10) |
                           ((128u / 8) << 17) | ((128u / 16) << 24);

    int ph0 = 0, ph1 = 0;   // per-stage-barrier phase counters

    auto load_chunk = [&](int c, int st) {
        const uint32_t s_a = salign + st * TG_STAGE_BYTES;
        const uint32_t s_b = s_a + 16384;
#pragma unroll
        for (int i = 0; i < 8; i++) {
            const int row = r0 + i * 16;
            unsigned off = row * 128 + c4 * 16;
            unsigned sw = off ^ ((off >> 3) & 0x70);
            cp_async16(s_a + sw, Ap + (size_t)(i * 16) * lda + c * 32);
            cp_async16(s_b + sw, Bp + (size_t)(i * 16) * ldb + c * 32);
        }
        cp_async_commit();
    };

    auto wait_stage = [&](int b) {
        if (b == 0) { mbar_wait_parity(s_mbar0, (unsigned)(ph0 & 1)); ph0++; }
        else        { mbar_wait_parity(s_mbar1, (unsigned)(ph1 & 1)); ph1++; }
    };

    const bool leader = (wid == 0) && elect_one();

    load_chunk(0, 0);   // prologue

    for (int c = 0; c < nch; c++) {
        const int st = c & 1;
        // chunk c's cp.async group is the only one outstanding
        cp_async_wait_all();
        asm volatile("fence.proxy.async.shared::cta;" ::: "memory");
        __syncthreads();

        if (leader) {
            const uint32_t s_a = salign + st * TG_STAGE_BYTES;
            const uint64_t adesc = smem_desc_sw128(s_a);
            const uint64_t bdesc = smem_desc_sw128(s_a + 16384);
#pragma unroll
            for (int ks = 0; ks < 4; ks++) {
                mma_tf32_ss(tmem, adesc + ks * 2, bdesc + ks * 2, idesc,
                            (c > 0 || ks > 0) ? 1u : 0u);
            }
            const uint32_t mb = st ? s_mbar1 : s_mbar0;
            asm volatile(
                "tcgen05.commit.cta_group::1.mbarrier::arrive::one.shared::cluster.b64 [%0];"
                :: "r"(mb) : "memory");
        }

        if (c + 1 < nch) {
            // stage st^1 was read by MMA of chunk c-1; wait its commit
            if (c >= 1) wait_stage(st ^ 1);
            load_chunk(c + 1, st ^ 1);   // overlaps MMA of chunk c
        }
    }

    // wait for last chunk's commit (implies all prior MMAs done)
    wait_stage((nch - 1) & 1);
    asm volatile("tcgen05.fence::after_thread_sync;" ::: "memory");

    const int row = bm + wid * 32 + lane;
    float* Crow = C + (size_t)row * ldc + bn;
#pragma unroll
    for (int g = 0; g < 4; g++) {
        uint32_t d[32];
        asm volatile(
            "tcgen05.ld.sync.aligned.32x32b.x32.b32 "
            "{%0,%1,%2,%3,%4,%5,%6,%7,%8,%9,%10,%11,%12,%13,%14,%15,"
            "%16,%17,%18,%19,%20,%21,%22,%23,%24,%25,%26,%27,%28,%29,%30,%31}, [%32];"
            : "=r"(d[0]), "=r"(d[1]), "=r"(d[2]), "=r"(d[3]),
              "=r"(d[4]), "=r"(d[5]), "=r"(d[6]), "=r"(d[7]),
              "=r"(d[8]), "=r"(d[9]), "=r"(d[10]), "=r"(d[11]),
              "=r"(d[12]), "=r"(d[13]), "=r"(d[14]), "=r"(d[15]),
              "=r"(d[16]), "=r"(d[17]), "=r"(d[18]), "=r"(d[19]),
              "=r"(d[20]), "=r"(d[21]), "=r"(d[22]), "=r"(d[23]),
              "=r"(d[24]), "=r"(d[25]), "=r"(d[26]), "=r"(d[27]),
              "=r"(d[28]), "=r"(d[29]), "=r"(d[30]), "=r"(d[31])
            : "r"(tmem + g * 32));
        asm volatile("tcgen05.wait::ld.sync.aligned;" ::: "memory");
#pragma unroll
        for (int v = 0; v < 8; v++) {
            const int col0 = g * 32 + v * 4;
            float4 o;
            o.x = epi_apply(__uint_as_float(d[v * 4 + 0]), bias, bn + col0 + 0);
            o.y = epi_apply(__uint_as_float(d[v * 4 + 1]), bias, bn + col0 + 1);
            o.z = epi_apply(__uint_as_float(d[v * 4 + 2]), bias, bn + col0 + 2);
            o.w = epi_apply(__uint_as_float(d[v * 4 + 3]), bias, bn + col0 + 3);
            *(float4*)(Crow + col0) = o;
        }
    }

    __syncthreads();
    if (tid == 0) { mbar_inval(s_mbar0); mbar_inval(s_mbar1); }
    __syncthreads();
    if (wid == 0) {
        asm volatile("tcgen05.dealloc.cta_group::1.sync.aligned.b32 %0, %1;"
                     :: "r"(tmem), "r"(128u));
    }
#else
    // ------------------ mma.sync fallback (generic sm_103 pass) ------------
    unsigned* As = (unsigned*)(dynbuf) + (salign - sbase) / 4;
    unsigned* Bs = As + 128 * 32;

    const int wm = wid * 32;
    const int q = lane & 3;
    const int r = lane >> 2;

    float acc[2][16][4];
#pragma unroll
    for (int i = 0; i < 2; i++)
#pragma unroll
        for (int j = 0; j < 16; j++)
#pragma unroll
            for (int t = 0; t < 4; t++) acc[i][j][t] = 0.f;

    for (int c = 0; c < nch; c++) {
        __syncthreads();
#pragma unroll
        for (int i = 0; i < 8; i++) {
            const int row = r0 + i * 16;
            uint4 av = *(const uint4*)(Ap + (size_t)(i * 16) * lda + c * 32);
            uint4 bv = *(const uint4*)(Bp + (size_t)(i * 16) * ldb + c * 32);
            *(uint4*)&As[row * 32 + c4 * 4] = av;
            *(uint4*)&Bs[row * 32 + c4 * 4] = bv;
        }
        __syncthreads();

#pragma unroll
        for (int kk = 0; kk < 32; kk += 8) {
            unsigned af[2][4];
#pragma unroll
            for (int i = 0; i < 2; i++) {
                const int mrow = wm + i * 16;
                af[i][0] = As[(mrow + r) * 32 + kk + q];
                af[i][1] = As[(mrow + r + 8) * 32 + kk + q];
                af[i][2] = As[(mrow + r) * 32 + kk + q + 4];
                af[i][3] = As[(mrow + r + 8) * 32 + kk + q + 4];
            }
#pragma unroll
            for (int j = 0; j < 16; j++) {
                unsigned bf[2];
                bf[0] = Bs[(j * 8 + r) * 32 + kk + q];
                bf[1] = Bs[(j * 8 + r) * 32 + kk + q + 4];
#pragma unroll
                for (int i = 0; i < 2; i++)
                    mma_m16n8k8_tf32(acc[i][j], af[i], bf);
            }
        }
    }

#pragma unroll
    for (int i = 0; i < 2; i++) {
        const int row = bm + wm + i * 16 + r;
#pragma unroll
        for (int j = 0; j < 16; j++) {
            const int col = bn + j * 8 + q * 2;
            float2 o0 = make_float2(epi_apply(acc[i][j][0], bias, col),
                                    epi_apply(acc[i][j][1], bias, col + 1));
            float2 o1 = make_float2(epi_apply(acc[i][j][2], bias, col),
                                    epi_apply(acc[i][j][3], bias, col + 1));
            *(float2*)&C[(size_t)row * ldc + col] = o0;
            *(float2*)&C[(size_t)(row + 8) * ldc + col] = o1;
        }
    }
#endif
}

// ---------------------------------------------------------------------------
// Depthwise causal conv (k=4) + bias + SiLU — dual fp32/tf32 output
// ---------------------------------------------------------------------------
__global__ void conv_silu_kernel(const float* __restrict__ xz,
                                 const float* __restrict__ cw,
                                 const float* __restrict__ cb,
                                 float* __restrict__ xsc,
                                 unsigned* __restrict__ xsc_t)
{
    const int idx = blockIdx.x * blockDim.x + threadIdx.x;
    if (idx >= MROWS * DINNER) return;
    const int d = idx & (DINNER - 1);
    const int m = idx >> 11;
    const int l = m & (LSEQ - 1);

    const float w0 = cw[d * 4 + 0], w1 = cw[d * 4 + 1];
    const float w2 = cw[d * 4 + 2], w3 = cw[d * 4 + 3];
    const float* p = xz + (size_t)m * NXZ + d;

    float acc = cb[d] + w3 * p[0];
    if (l >= 1) acc = fmaf(w2, p[-NXZ],     acc);
    if (l >= 2) acc = fmaf(w1, p[-2 * NXZ], acc);
    if (l >= 3) acc = fmaf(w0, p[-3 * NXZ], acc);

    const float v = acc / (1.f + __expf(-acc));
    xsc[idx] = v;
    xsc_t[idx] = f2tf32(v);
}

// ---------------------------------------------------------------------------
// Split-K reductions
// ---------------------------------------------------------------------------
__global__ void reduce_dbc_kernel(const float* __restrict__ part,
                                  float* __restrict__ out,
                                  unsigned* __restrict__ out_t)
{
    const int idx = blockIdx.x * blockDim.x + threadIdx.x;
    if (idx >= MROWS * NDBC) return;
    const int row = idx / NDBC;
    const int col = idx - row * NDBC;
    float s = 0.f;
#pragma unroll
    for (int j = 0; j < SPLITK_XPROJ; j++)
        s += part[(size_t)j * MROWS * NDBC_PAD + (size_t)row * NDBC_PAD + col];
    out[idx] = s;
    out_t[idx] = f2tf32(s);
}

__global__ void reduce_out_kernel(const float* __restrict__ part,
                                  float* __restrict__ out)
{
    const int idx = blockIdx.x * blockDim.x + threadIdx.x;
    if (idx >= MROWS * DMODEL) return;
    out[idx] = part[idx] + part[(size_t)MROWS * DMODEL + idx];
}

// ---------------------------------------------------------------------------
// Selective scan v3 (phase-split recurrence; see R11)
// ---------------------------------------------------------------------------
#define SCH   16   // channels per CTA
#define SCHK  16   // l-steps per chunk

__global__ void __launch_bounds__(256) scan_kernel(
    const float* __restrict__ delta,
    const float* __restrict__ xsc,
    const float* __restrict__ dbc,
    const float* __restrict__ xz,
    const float* __restrict__ A_log,
    const float* __restrict__ Dp,
    unsigned* __restrict__ yt)
{
    __shared__ float sD[SCHK][SCH];
    __shared__ float sX[SCHK][SCH];
    __shared__ float sZ[SCHK][SCH];
    __shared__ float sB[SCHK][DSTATE];
    __shared__ float sC[SCHK][DSTATE];
    __shared__ unsigned sY[SCHK][SCH];

    const int tid = threadIdx.x;
    const int ch  = tid >> 4;
    const int n   = tid & 15;
    const int b   = blockIdx.x >> 7;
    const int d0  = (blockIdx.x & 127) * SCH;

    const int lrow = tid >> 4;
    const int lcol = tid & 15;

    const float An = -__expf(A_log[(d0 + ch) * DSTATE + n]);
    const float Dd = Dp[d0 + ch];

    const size_t rowD = (size_t)DINNER;

    float rD, rX, rZ, rB, rC;
    auto issue_loads = [&](int j) {
        const size_t m = (size_t)b * LSEQ + j * SCHK + lrow;
        rD = delta[m * rowD + d0 + lcol];
        rX = xsc  [m * rowD + d0 + lcol];
        rZ = xz   [m * NXZ + DINNER + d0 + lcol];
        rB = dbc  [m * NDBC + DTRANK + lcol];
        rC = dbc  [m * NDBC + DTRANK + DSTATE + lcol];
    };

    issue_loads(0);
    sD[lrow][lcol] = rD; sX[lrow][lcol] = rX; sZ[lrow][lcol] = rZ;
    sB[lrow][lcol] = rB; sC[lrow][lcol] = rC;
    __syncthreads();

    float h = 0.f;
    const int nchk = LSEQ / SCHK;
    for (int j = 0; j < nchk; j++) {
        if (j + 1 < nchk) issue_loads(j + 1);

        float dA[SCHK], dBx[SCHK], hC[SCHK];
#pragma unroll
        for (int s = 0; s < SCHK; s++) {
            const float dl = sD[s][ch];
            const float xv = sX[s][ch];
            dA[s]  = __expf(dl * An);
            dBx[s] = dl * xv * sB[s][n];
        }

#pragma unroll
        for (int s = 0; s < SCHK; s++) {
            h = fmaf(dA[s], h, dBx[s]);
            hC[s] = h * sC[s][n];
        }

#pragma unroll
        for (int s = 0; s < SCHK; s++) {
            float part = hC[s];
            part += __shfl_xor_sync(0xffffffffu, part, 8, 16);
            part += __shfl_xor_sync(0xffffffffu, part, 4, 16);
            part += __shfl_xor_sync(0xffffffffu, part, 2, 16);
            part += __shfl_xor_sync(0xffffffffu, part, 1, 16);

            if (n == 0) {
                const float yv = part + Dd * sX[s][ch];
                const float zv = sZ[s][ch];
                const float sz = zv / (1.f + __expf(-zv));
                sY[s][ch] = f2tf32(yv * sz);
            }
        }
        __syncthreads();

        {
            const size_t m = (size_t)b * LSEQ + j * SCHK + lrow;
            yt[m * rowD + d0 + lcol] = sY[lrow][lcol];
        }

        if (j + 1 < nchk) {
            sD[lrow][lcol] = rD; sX[lrow][lcol] = rX; sZ[lrow][lcol] = rZ;
            sB[lrow][lcol] = rB; sC[lrow][lcol] = rC;
        }
        __syncthreads();
    }
}

// ---------------------------------------------------------------------------
// Launch
// ---------------------------------------------------------------------------
extern "C" void kernel_launch(void* const* d_in, const int* in_sizes, int n_in,
                              void* d_out, int out_size)
{
    const float* x         = (const float*)d_in[0];
    const float* in_proj_w = (const float*)d_in[1];
    const float* conv_w    = (const float*)d_in[2];
    const float* conv_b    = (const float*)d_in[3];
    const float* x_proj_w  = (const float*)d_in[4];
    const float* dt_proj_w = (const float*)d_in[5];
    const float* dt_proj_b = (const float*)d_in[6];
    const float* A_log     = (const float*)d_in[7];
    const float* Dvec      = (const float*)d_in[8];
    const float* out_proj_w= (const float*)d_in[9];
    float* out = (float*)d_out;

    float *xz, *xsc, *dbc_part, *dbc, *delta, *opart;
    unsigned *xsc_t, *dbc_t, *xt, *wt_in, *wt_out, *wt_xp, *wt_dt, *yt;
    cudaGetSymbolAddress((void**)&xz,       g_xz);
    cudaGetSymbolAddress((void**)&xsc,      g_xsc);
    cudaGetSymbolAddress((void**)&xsc_t,    g_xsc_t);
    cudaGetSymbolAddress((void**)&dbc_part, g_dbc_part);
    cudaGetSymbolAddress((void**)&dbc,      g_dbc);
    cudaGetSymbolAddress((void**)&dbc_t,    g_dbc_t);
    cudaGetSymbolAddress((void**)&delta,    g_delta);
    cudaGetSymbolAddress((void**)&xt,       g_xt);
    cudaGetSymbolAddress((void**)&wt_in,    g_wt_in);
    cudaGetSymbolAddress((void**)&wt_out,   g_wt_out);
    cudaGetSymbolAddress((void**)&wt_xp,    g_wt_xp);
    cudaGetSymbolAddress((void**)&wt_dt,    g_wt_dt);
    cudaGetSymbolAddress((void**)&yt,       g_yt);
    cudaGetSymbolAddress((void**)&opart,    g_opart);

    cudaFuncSetAttribute(tgemm_tc, cudaFuncAttributeMaxDynamicSharedMemorySize,
                         TG_SMEM_BYTES);

    // 0) pre-convert fp32 -> tf32 (one fused launch)
    {
        const int na4 = (MROWS * DMODEL) / 4;
        const int nb4 = (NXZ * DMODEL) / 4;
        const int nc4 = (DMODEL * DINNER) / 4;
        const int nx4 = (NDBC_PAD * DINNER) / 4;
        const int nd4 = (DINNER * DTRANK) / 4;
        const int tot = na4 + nb4 + nc4 + nx4 + nd4;
        cvt5_tf32_kernel<<<(tot + 255) / 256, 256>>>(
            (const float4*)x, (uint4*)xt, na4,
            (const float4*)in_proj_w, (uint4*)wt_in, nb4,
            (const float4*)out_proj_w, (uint4*)wt_out, nc4,
            (const float4*)x_proj_w, (uint4*)wt_xp, nx4,
            (const float4*)dt_proj_w, (uint4*)wt_dt, nd4);
    }

    // 1) xz = x @ in_proj_w^T  (2048 x 4096, K=1024) — pipelined tcgen05
    {
        dim3 grid(NXZ / 128, MROWS / 128, 1);
        tgemm_tc<<<grid, 128, TG_SMEM_BYTES>>>(xt, wt_in, xz,
                                               DMODEL, DMODEL, NXZ,
                                               DMODEL, 0, nullptr);
    }

    // 2) depthwise conv + bias + silu -> xsc (fp32) + xsc_t (tf32)
    {
        int n = MROWS * DINNER;
        conv_silu_kernel<<<(n + 255) / 256, 256>>>(xz, conv_w, conv_b, xsc, xsc_t);
    }

    // 3) dbc = xsc @ x_proj_w^T  (2048 x 96pad128, K=2048) — split-K=16
    {
        dim3 grid(1, MROWS / 128, SPLITK_XPROJ);
        tgemm_tc<<<grid, 128, TG_SMEM_BYTES>>>(xsc_t, wt_xp, dbc_part,
                                               DINNER, DINNER, NDBC_PAD,
                                               DINNER / SPLITK_XPROJ,
                                               (size_t)MROWS * NDBC_PAD, nullptr);
        int n = MROWS * NDBC;
        reduce_dbc_kernel<<<(n + 255) / 256, 256>>>(dbc_part, dbc, dbc_t);
    }

    // 4) delta = softplus(dbc[:, :64] @ dt_proj_w^T + dt_proj_b) — tcgen05 + epi
    {
        dim3 grid(DINNER / 128, MROWS / 128, 1);
        tgemm_tc<<<grid, 128, TG_SMEM_BYTES>>>(dbc_t, wt_dt, delta,
                                               NDBC, DTRANK, DINNER,
                                               DTRANK, 0, dt_proj_b);
    }

    // 5) selective scan v3 -> yt (tf32)
    {
        int blocks = (BSZ * DINNER) / SCH;
        scan_kernel<<<blocks, 256>>>(delta, xsc, dbc, xz, A_log, Dvec, yt);
    }

    // 6) out = y @ out_proj_w^T  (2048 x 1024, K=2048) — split-K=2
    {
        dim3 grid(DMODEL / 128, MROWS / 128, SPLITK_OPROJ);
        tgemm_tc<<<grid, 128, TG_SMEM_BYTES>>>(yt, wt_out, opart,
                                               DINNER, DINNER, DMODEL,
                                               DINNER / SPLITK_OPROJ,
                                               (size_t)MROWS * DMODEL, nullptr);
        int n = MROWS * DMODEL;
        reduce_out_kernel<<<(n + 255) / 256, 256>>>(opart, out);
    }
}